// round 1
// baseline (speedup 1.0000x reference)
#include <cuda_runtime.h>
#include <math.h>

// ---------------- sizes ----------------
// B=256, b3=768, D=1280, C=64, WIN=14, N=196, NH=8, HD=8, A=49
#define B3    768
#define NTOK  196
#define NHD   8
#define NAG   49

constexpr size_t SZ_XT    = 768ull * 12544;        // (b3, N*C)
constexpr size_t SZ_QKV   = 768ull * 196 * 192;
constexpr size_t SZ_O     = 768ull * 12544;
constexpr size_t SZ_T     = 768ull * 12544;
constexpr size_t SZ_OPROJ = 768ull * 12544;
constexpr size_t SZ_PB    = 8ull * 49 * 196;
constexpr size_t SZ_AB    = 8ull * 196 * 49;
constexpr size_t SZ_H     = 768ull * 256;
constexpr size_t SZ_SCR   = 16ull * 768 * 256;

constexpr size_t OFF_XT    = 0;
constexpr size_t OFF_QKV   = OFF_XT + SZ_XT;
constexpr size_t OFF_O     = OFF_QKV + SZ_QKV;
constexpr size_t OFF_T     = OFF_O + SZ_O;
constexpr size_t OFF_OPROJ = OFF_T + SZ_T;
constexpr size_t OFF_PB    = OFF_OPROJ + SZ_OPROJ;
constexpr size_t OFF_AB    = OFF_PB + SZ_PB;
constexpr size_t OFF_H     = OFF_AB + SZ_AB;
constexpr size_t OFF_SCR   = OFF_H + SZ_H;
constexpr size_t WS_TOTAL  = OFF_SCR + SZ_SCR;

__device__ __align__(256) float g_ws[WS_TOTAL];

// ---------------- generic NT GEMM: C = A(MxK,row) * B(NxK,row)^T ----------------
// grid = (N/BN, M/BM, splitK). Each z-slice computes a kChunk of K into
// C + z*M*N. bias (length N) added only on z==0 slice.
template<int BM, int BN, int TM, int TN>
__global__ void __launch_bounds__(256)
gemm_nt(const float* __restrict__ A, const float* __restrict__ B,
        const float* __restrict__ bias, float* __restrict__ C,
        int M, int N, int K, int kChunk) {
    constexpr int BK = 8;
    __shared__ float As[BK][BM];
    __shared__ float Bs[BK][BN];
    const int tid = threadIdx.x;
    const int kBase = blockIdx.z * kChunk;
    const float* Ab = A + (size_t)blockIdx.y * BM * K + kBase;
    const float* Bb = B + (size_t)blockIdx.x * BN * K + kBase;
    float acc[TM][TN];
#pragma unroll
    for (int i = 0; i < TM; i++)
#pragma unroll
        for (int j = 0; j < TN; j++) acc[i][j] = 0.f;

    const int tRow = (tid / (BN / TN)) * TM;
    const int tCol = (tid % (BN / TN)) * TN;

    for (int kt = 0; kt < kChunk; kt += BK) {
        for (int i = tid; i < BM * 2; i += 256) {
            int row = i >> 1, c4 = (i & 1) << 2;
            float4 v = *(const float4*)(Ab + (size_t)row * K + kt + c4);
            As[c4 + 0][row] = v.x; As[c4 + 1][row] = v.y;
            As[c4 + 2][row] = v.z; As[c4 + 3][row] = v.w;
        }
        for (int i = tid; i < BN * 2; i += 256) {
            int row = i >> 1, c4 = (i & 1) << 2;
            float4 v = *(const float4*)(Bb + (size_t)row * K + kt + c4);
            Bs[c4 + 0][row] = v.x; Bs[c4 + 1][row] = v.y;
            Bs[c4 + 2][row] = v.z; Bs[c4 + 3][row] = v.w;
        }
        __syncthreads();
#pragma unroll
        for (int k = 0; k < BK; k++) {
            float ra[TM], rb[TN];
#pragma unroll
            for (int i = 0; i < TM; i += 4)
                *(float4*)&ra[i] = *(const float4*)&As[k][tRow + i];
#pragma unroll
            for (int j = 0; j < TN; j += 4)
                *(float4*)&rb[j] = *(const float4*)&Bs[k][tCol + j];
#pragma unroll
            for (int i = 0; i < TM; i++)
#pragma unroll
                for (int j = 0; j < TN; j++)
                    acc[i][j] += ra[i] * rb[j];
        }
        __syncthreads();
    }

    float* Cb = C + (size_t)blockIdx.z * M * N
                  + (size_t)(blockIdx.y * BM + tRow) * N + blockIdx.x * BN + tCol;
    const bool addb = (bias != nullptr) && (blockIdx.z == 0);
#pragma unroll
    for (int i = 0; i < TM; i++)
#pragma unroll
        for (int j = 0; j < TN; j++) {
            float v = acc[i][j];
            if (addb) v += bias[blockIdx.x * BN + tCol + j];
            Cb[(size_t)i * N + j] = v;
        }
}

// ---------------- bilinear-resized position biases ----------------
// pb[h][a][n] (stage1), ab[h][n][a] (stage2)
__global__ void bias_resize_kernel(const float* __restrict__ an, const float* __restrict__ na,
                                   const float* __restrict__ ah, const float* __restrict__ aw,
                                   const float* __restrict__ ha, const float* __restrict__ wa,
                                   float* __restrict__ pb, float* __restrict__ ab) {
    int i = blockIdx.x * 256 + threadIdx.x;
    if (i >= NHD * NAG * NTOK) return;
    int h = i / (NAG * NTOK);
    int rem = i % (NAG * NTOK);
    int a = rem / NTOK;
    int n = rem % NTOK;
    int r = n / 14, c = n % 14;

    auto coord = [](int j, int& i0, int& i1, float& w) {
        float src = (j + 0.5f) * 0.5f - 0.5f;
        src = fmaxf(src, 0.f);
        src = fminf(src, 6.f);
        i0 = (int)floorf(src);
        i1 = min(i0 + 1, 6);
        w = src - (float)i0;
    };
    int r0, r1, c0, c1; float wr, wc;
    coord(r, r0, r1, wr);
    coord(c, c0, c1, wc);

    const float* T1 = an + ((size_t)h * NAG + a) * 49;
    float v1 = (1.f - wr) * ((1.f - wc) * T1[r0 * 7 + c0] + wc * T1[r0 * 7 + c1])
             + wr * ((1.f - wc) * T1[r1 * 7 + c0] + wc * T1[r1 * 7 + c1]);
    pb[((size_t)h * NAG + a) * NTOK + n] =
        v1 + ah[((size_t)h * NAG + a) * 14 + r] + aw[((size_t)h * NAG + a) * 14 + c];

    const float* T2 = na + ((size_t)h * NAG + a) * 49;
    float v2 = (1.f - wr) * ((1.f - wc) * T2[r0 * 7 + c0] + wc * T2[r0 * 7 + c1])
             + wr * ((1.f - wc) * T2[r1 * 7 + c0] + wc * T2[r1 * 7 + c1]);
    ab[((size_t)h * NTOK + n) * NAG + a] =
        v2 + ha[((size_t)h * 14 + r) * NAG + a] + wa[((size_t)h * 14 + c) * NAG + a];
}

// ---------------- agent attention: one block per (b, h) ----------------
__global__ void __launch_bounds__(256)
attn_kernel(const float* __restrict__ qkv, const float* __restrict__ pb,
            const float* __restrict__ ab, float* __restrict__ o_out) {
    extern __shared__ float sm[];
    float* qs = sm;             // 1568
    float* ks = qs + 1568;      // 1568
    float* vs = ks + 1568;      // 1568
    float* ag = vs + 1568;      // 392
    float* av = ag + 392;       // 392
    float* S  = av + 392;       // 9604

    const int b = blockIdx.x / NHD, h = blockIdx.x % NHD;
    const int tid = threadIdx.x;
    const float scale = 0.35355339059327373f;   // 8^-0.5
    const float* base = qkv + (size_t)b * NTOK * 192;

    for (int i = tid; i < 1568; i += 256) {
        int n = i >> 3, d = i & 7;
        qs[i] = base[n * 192 + h * 8 + d];
        ks[i] = base[n * 192 + 64 + h * 8 + d];
        vs[i] = base[n * 192 + 128 + h * 8 + d];
    }
    __syncthreads();

    // agent tokens: exact 2x2 mean pool of q on the 14x14 grid
    for (int i = tid; i < 392; i += 256) {
        int a = i >> 3, d = i & 7;
        int ar = a / 7, ac = a % 7;
        int n0 = (2 * ar) * 14 + 2 * ac;
        ag[i] = 0.25f * (qs[n0 * 8 + d] + qs[(n0 + 1) * 8 + d] +
                         qs[(n0 + 14) * 8 + d] + qs[(n0 + 15) * 8 + d]);
    }
    __syncthreads();

    // stage 1: S[a][n] = scale * agent.k + pb
    const float* pbh = pb + (size_t)h * NAG * NTOK;
    for (int i = tid; i < NAG * NTOK; i += 256) {
        int a = i / NTOK, n = i % NTOK;
        float s = 0.f;
#pragma unroll
        for (int d = 0; d < 8; d++) s += ag[a * 8 + d] * ks[n * 8 + d];
        S[i] = s * scale + pbh[i];
    }
    __syncthreads();

    // softmax over n (warp per row)
    const int warp = tid >> 5, lane = tid & 31;
    for (int a = warp; a < NAG; a += 8) {
        float* row = S + a * NTOK;
        float m = -1e30f;
        for (int n = lane; n < NTOK; n += 32) m = fmaxf(m, row[n]);
#pragma unroll
        for (int o = 16; o; o >>= 1) m = fmaxf(m, __shfl_xor_sync(0xffffffffu, m, o));
        float sum = 0.f;
        for (int n = lane; n < NTOK; n += 32) {
            float e = __expf(row[n] - m); row[n] = e; sum += e;
        }
#pragma unroll
        for (int o = 16; o; o >>= 1) sum += __shfl_xor_sync(0xffffffffu, sum, o);
        float inv = 1.f / sum;
        for (int n = lane; n < NTOK; n += 32) row[n] *= inv;
    }
    __syncthreads();

    // agent_v[a][d]
    for (int i = tid; i < 392; i += 256) {
        int a = i >> 3, d = i & 7;
        const float* row = S + a * NTOK;
        float s = 0.f;
        for (int n = 0; n < NTOK; n++) s += row[n] * vs[n * 8 + d];
        av[i] = s;
    }
    __syncthreads();

    // stage 2: S[n][a] = scale * q.agent + ab
    const float* abh = ab + (size_t)h * NTOK * NAG;
    for (int i = tid; i < NTOK * NAG; i += 256) {
        int n = i / NAG, a = i % NAG;
        float s = 0.f;
#pragma unroll
        for (int d = 0; d < 8; d++) s += qs[n * 8 + d] * ag[a * 8 + d];
        S[i] = s * scale + abh[i];
    }
    __syncthreads();

    // softmax over a (thread per row)
    for (int n = tid; n < NTOK; n += 256) {
        float* row = S + n * NAG;
        float m = -1e30f;
        for (int a = 0; a < NAG; a++) m = fmaxf(m, row[a]);
        float sum = 0.f;
        for (int a = 0; a < NAG; a++) { float e = __expf(row[a] - m); row[a] = e; sum += e; }
        float inv = 1.f / sum;
        for (int a = 0; a < NAG; a++) row[a] *= inv;
    }
    __syncthreads();

    // o[n][d] -> global (b, n, h*8+d)
    float* ob = o_out + (size_t)b * NTOK * 64;
    for (int i = tid; i < 1568; i += 256) {
        int n = i >> 3, d = i & 7;
        const float* row = S + n * NAG;
        float s = 0.f;
        for (int a = 0; a < NAG; a++) s += row[a] * av[a * 8 + d];
        ob[n * 64 + h * 8 + d] = s;
    }
}

// ---------------- depthwise 3x3 conv on v + residual add ----------------
__global__ void __launch_bounds__(256)
dwc_kernel(const float* __restrict__ qkv, const float* __restrict__ o_in,
           const float* __restrict__ dwc_w, const float* __restrict__ dwc_b,
           float* __restrict__ t_out) {
    extern __shared__ float vsm[];   // 196*64
    const int b = blockIdx.x, tid = threadIdx.x;
    const float* base = qkv + (size_t)b * NTOK * 192 + 128;
    for (int i = tid; i < 12544; i += 256) {
        int n = i >> 6, c = i & 63;
        vsm[i] = base[n * 192 + c];
    }
    __syncthreads();
    const float* ob = o_in + (size_t)b * 12544;
    float* tb = t_out + (size_t)b * 12544;
    for (int i = tid; i < 12544; i += 256) {
        int n = i >> 6, c = i & 63;
        int r = n / 14, col = n % 14;
        float acc = ob[i] + dwc_b[c];
#pragma unroll
        for (int dr = -1; dr <= 1; dr++) {
            int rr = r + dr;
            if (rr < 0 || rr > 13) continue;
#pragma unroll
            for (int dc = -1; dc <= 1; dc++) {
                int cc = col + dc;
                if (cc < 0 || cc > 13) continue;
                acc += dwc_w[c * 9 + (dr + 1) * 3 + (dc + 1)] * vsm[(rr * 14 + cc) * 64 + c];
            }
        }
        tb[i] = acc;
    }
}

// ---------------- split-K reduces ----------------
__global__ void reduce_adj(const float* __restrict__ part, float* __restrict__ out) {
    int i = blockIdx.x * 256 + threadIdx.x;
    if (i >= 768 * 256) return;
    float s = 0.f;
#pragma unroll
    for (int z = 0; z < 16; z++) s += part[(size_t)z * 768 * 256 + i];
    out[i] = s;     // X_adj region (bias already folded into z==0 slice)
}

__global__ void reduce_tanh(const float* __restrict__ part, float* __restrict__ hbuf) {
    int i = blockIdx.x * 256 + threadIdx.x;
    if (i >= 768 * 256) return;
    float s = 0.f;
#pragma unroll
    for (int z = 0; z < 8; z++) s += part[(size_t)z * 768 * 256 + i];
    hbuf[i] = tanhf(s);
}

__global__ void reduce_t2(const float* __restrict__ part, float* __restrict__ dout) {
    int i = blockIdx.x * 256 + threadIdx.x;
    if (i >= 768 * 128) return;
    float s = 0.f;
#pragma unroll
    for (int z = 0; z < 4; z++) s += part[(size_t)z * 768 * 128 + i];
    int r = i >> 7, j = i & 127;
    int b = r / 3, which = r % 3;   // anchor / pos / neg
    dout[(size_t)which * 32768 + b * 128 + j] = s;
}

// ---------------- launch ----------------
extern "C" void kernel_launch(void* const* d_in, const int* in_sizes, int n_in,
                              void* d_out, int out_size) {
    (void)in_sizes; (void)n_in; (void)out_size;
    const float* X       = (const float*)d_in[0];
    const float* W_embed = (const float*)d_in[1];
    const float* b_embed = (const float*)d_in[2];
    const float* W_qkv   = (const float*)d_in[3];
    const float* W_proj  = (const float*)d_in[4];
    const float* b_proj  = (const float*)d_in[5];
    const float* dwc_w   = (const float*)d_in[6];
    const float* dwc_b   = (const float*)d_in[7];
    const float* an_bias = (const float*)d_in[8];
    const float* na_bias = (const float*)d_in[9];
    const float* ah_bias = (const float*)d_in[10];
    const float* aw_bias = (const float*)d_in[11];
    const float* ha_bias = (const float*)d_in[12];
    const float* wa_bias = (const float*)d_in[13];
    const float* W_adj   = (const float*)d_in[14];
    const float* b_adj   = (const float*)d_in[15];
    const float* W_t1    = (const float*)d_in[16];
    const float* b_t1    = (const float*)d_in[17];
    const float* W_t2    = (const float*)d_in[18];
    const float* b_t2    = (const float*)d_in[19];
    float* out = (float*)d_out;

    float* ws = nullptr;
    cudaGetSymbolAddress((void**)&ws, g_ws);
    float* xt    = ws + OFF_XT;
    float* qkv   = ws + OFF_QKV;
    float* obuf  = ws + OFF_O;
    float* tbuf  = ws + OFF_T;
    float* oproj = ws + OFF_OPROJ;
    float* pb    = ws + OFF_PB;
    float* ab    = ws + OFF_AB;
    float* hbuf  = ws + OFF_H;
    float* scr   = ws + OFF_SCR;

    const int ATTN_SMEM = (1568 * 3 + 392 * 2 + 9604) * 4;   // 58768 B
    const int DWC_SMEM  = 12544 * 4;                          // 50176 B
    cudaFuncSetAttribute(attn_kernel, cudaFuncAttributeMaxDynamicSharedMemorySize, ATTN_SMEM);
    cudaFuncSetAttribute(dwc_kernel,  cudaFuncAttributeMaxDynamicSharedMemorySize, DWC_SMEM);

    // position biases (tiny)
    bias_resize_kernel<<<(NHD * NAG * NTOK + 255) / 256, 256>>>(
        an_bias, na_bias, ah_bias, aw_bias, ha_bias, wa_bias, pb, ab);

    // embed: (768,1280) x (12544,1280)^T + b  -> xt
    gemm_nt<128, 128, 8, 8><<<dim3(98, 6, 1), 256>>>(
        X, W_embed, b_embed, xt, 768, 12544, 1280, 1280);

    // qkv: (150528,64) x (192,64)^T -> qkv
    gemm_nt<128, 64, 8, 4><<<dim3(3, 1176, 1), 256>>>(
        xt, W_qkv, nullptr, qkv, 150528, 192, 64, 64);

    // agent attention
    attn_kernel<<<B3 * NHD, 256, ATTN_SMEM>>>(qkv, pb, ab, obuf);

    // dwc + residual -> tbuf
    dwc_kernel<<<B3, 256, DWC_SMEM>>>(qkv, obuf, dwc_w, dwc_b, tbuf);

    // proj: (150528,64) x (64,64)^T + b -> oproj
    gemm_nt<128, 64, 8, 4><<<dim3(1, 1176, 1), 256>>>(
        tbuf, W_proj, b_proj, oproj, 150528, 64, 64, 64);

    // adj: (768,12544) x (256,12544)^T + b, split-K=16 -> scr, reduce -> X_adj
    gemm_nt<128, 128, 8, 8><<<dim3(2, 6, 16), 256>>>(
        oproj, W_adj, b_adj, scr, 768, 256, 12544, 784);
    reduce_adj<<<768, 256>>>(scr, out + 98304);

    // MLP layer 1: (768,1280) x (256,1280)^T + b, split-K=8, tanh -> hbuf
    gemm_nt<128, 128, 8, 8><<<dim3(2, 6, 8), 256>>>(
        X, W_t1, b_t1, scr, 768, 256, 1280, 160);
    reduce_tanh<<<768, 256>>>(scr, hbuf);

    // MLP layer 2: (768,256) x (128,256)^T + b, split-K=4 -> anchor/pos/neg
    gemm_nt<128, 64, 8, 4><<<dim3(2, 6, 4), 256>>>(
        hbuf, W_t2, b_t2, scr, 768, 128, 256, 64);
    reduce_t2<<<(768 * 128 + 255) / 256, 256>>>(scr, out);
}

// round 4
// speedup vs baseline: 1.7486x; 1.7486x over previous
#include <cuda_runtime.h>
#include <stdint.h>
#include <math.h>

// ---------------- sizes ----------------
// B=256, b3=768, D=1280, C=64, WIN=14, N=196, NH=8, HD=8, A=49
#define B3    768
#define NTOK  196
#define NHD   8
#define NAG   49

constexpr size_t SZ_XT    = 768ull * 12544;
constexpr size_t SZ_QKV   = 768ull * 196 * 192;
constexpr size_t SZ_O     = 768ull * 12544;
constexpr size_t SZ_T     = 768ull * 12544;
constexpr size_t SZ_OPROJ = 768ull * 12544;
constexpr size_t SZ_PB    = 8ull * 49 * 196;
constexpr size_t SZ_AB    = 8ull * 196 * 49;
constexpr size_t SZ_H     = 768ull * 256;
constexpr size_t SZ_SCR   = 16ull * 768 * 256;

constexpr size_t OFF_XT    = 0;
constexpr size_t OFF_QKV   = OFF_XT + SZ_XT;
constexpr size_t OFF_O     = OFF_QKV + SZ_QKV;
constexpr size_t OFF_T     = OFF_O + SZ_O;
constexpr size_t OFF_OPROJ = OFF_T + SZ_T;
constexpr size_t OFF_PB    = OFF_OPROJ + SZ_OPROJ;
constexpr size_t OFF_AB    = OFF_PB + SZ_PB;
constexpr size_t OFF_H     = OFF_AB + SZ_AB;
constexpr size_t OFF_SCR   = OFF_H + SZ_H;
constexpr size_t WS_TOTAL  = OFF_SCR + SZ_SCR;

__device__ __align__(256) float g_ws[WS_TOTAL];

__device__ __forceinline__ uint32_t f2tf32(float x) {
    uint32_t u;
    asm("cvt.rna.tf32.f32 %0, %1;" : "=r"(u) : "f"(x));
    return u;
}

// ---------------- tf32 tensor-core NT GEMM ----------------
// C = A(MxK,row) * B(NxK,row)^T ; grid=(N/BN, M/BM, splitZ), each z writes
// its kChunk partial into C + z*M*N. bias added on z==0 only.
template<int BM, int BN, int WM, int WN>
__global__ void __launch_bounds__(256)
gemm_tf32(const float* __restrict__ A, const float* __restrict__ B,
          const float* __restrict__ bias, float* __restrict__ C,
          int M, int N, int K, int kChunk) {
    constexpr int BK = 32;
    constexpr int WARPS_N = BN / WN;
    constexpr int MT = WM / 16;
    constexpr int NT = WN / 8;
    constexpr int LDA = BM + 4;
    constexpr int LDB = BN + 4;
    constexpr int A_ITERS = BM * BK / 1024;
    constexpr int B_ITERS = BN * BK / 1024;

    __shared__ float As[BK][LDA];
    __shared__ float Bs[BK][LDB];

    const int tid = threadIdx.x;
    const int lane = tid & 31;
    const int warp = tid >> 5;
    const int wr = (warp / WARPS_N) * WM;
    const int wc = (warp % WARPS_N) * WN;
    const int gid = lane >> 2;   // 0..7
    const int tg  = lane & 3;    // 0..3

    const int kBase = blockIdx.z * kChunk;
    const float* Ab = A + (size_t)blockIdx.y * BM * K + kBase;
    const float* Bb = B + (size_t)blockIdx.x * BN * K + kBase;

    float c[MT][NT][4];
#pragma unroll
    for (int i = 0; i < MT; i++)
#pragma unroll
        for (int j = 0; j < NT; j++)
#pragma unroll
            for (int r = 0; r < 4; r++) c[i][j][r] = 0.f;

    for (int kt = 0; kt < kChunk; kt += BK) {
#pragma unroll
        for (int it = 0; it < A_ITERS; it++) {
            int linear = tid + it * 256;
            int row = linear >> 3;
            int cv = (linear & 7) << 2;
            float4 v = *(const float4*)(Ab + (size_t)row * K + kt + cv);
            As[cv + 0][row] = __uint_as_float(f2tf32(v.x));
            As[cv + 1][row] = __uint_as_float(f2tf32(v.y));
            As[cv + 2][row] = __uint_as_float(f2tf32(v.z));
            As[cv + 3][row] = __uint_as_float(f2tf32(v.w));
        }
#pragma unroll
        for (int it = 0; it < B_ITERS; it++) {
            int linear = tid + it * 256;
            int row = linear >> 3;
            int cv = (linear & 7) << 2;
            float4 v = *(const float4*)(Bb + (size_t)row * K + kt + cv);
            Bs[cv + 0][row] = __uint_as_float(f2tf32(v.x));
            Bs[cv + 1][row] = __uint_as_float(f2tf32(v.y));
            Bs[cv + 2][row] = __uint_as_float(f2tf32(v.z));
            Bs[cv + 3][row] = __uint_as_float(f2tf32(v.w));
        }
        __syncthreads();

#pragma unroll
        for (int kk = 0; kk < 4; kk++) {
            uint32_t af[MT][4];
            uint32_t bf[NT][2];
#pragma unroll
            for (int mt = 0; mt < MT; mt++) {
                af[mt][0] = __float_as_uint(As[kk * 8 + tg][wr + mt * 16 + gid]);
                af[mt][1] = __float_as_uint(As[kk * 8 + tg][wr + mt * 16 + gid + 8]);
                af[mt][2] = __float_as_uint(As[kk * 8 + tg + 4][wr + mt * 16 + gid]);
                af[mt][3] = __float_as_uint(As[kk * 8 + tg + 4][wr + mt * 16 + gid + 8]);
            }
#pragma unroll
            for (int nt = 0; nt < NT; nt++) {
                bf[nt][0] = __float_as_uint(Bs[kk * 8 + tg][wc + nt * 8 + gid]);
                bf[nt][1] = __float_as_uint(Bs[kk * 8 + tg + 4][wc + nt * 8 + gid]);
            }
#pragma unroll
            for (int mt = 0; mt < MT; mt++)
#pragma unroll
                for (int nt = 0; nt < NT; nt++) {
                    asm volatile(
                        "mma.sync.aligned.m16n8k8.row.col.f32.tf32.tf32.f32 "
                        "{%0,%1,%2,%3}, {%4,%5,%6,%7}, {%8,%9}, {%0,%1,%2,%3};\n"
                        : "+f"(c[mt][nt][0]), "+f"(c[mt][nt][1]),
                          "+f"(c[mt][nt][2]), "+f"(c[mt][nt][3])
                        : "r"(af[mt][0]), "r"(af[mt][1]), "r"(af[mt][2]), "r"(af[mt][3]),
                          "r"(bf[nt][0]), "r"(bf[nt][1]));
                }
        }
        __syncthreads();
    }

    const bool addb = (bias != nullptr) && (blockIdx.z == 0);
    float* Cz = C + (size_t)blockIdx.z * M * N;
#pragma unroll
    for (int mt = 0; mt < MT; mt++) {
        int row0 = blockIdx.y * BM + wr + mt * 16 + gid;
#pragma unroll
        for (int nt = 0; nt < NT; nt++) {
            int col = blockIdx.x * BN + wc + nt * 8 + tg * 2;
            float b0 = addb ? bias[col] : 0.f;
            float b1 = addb ? bias[col + 1] : 0.f;
            Cz[(size_t)row0 * N + col]           = c[mt][nt][0] + b0;
            Cz[(size_t)row0 * N + col + 1]       = c[mt][nt][1] + b1;
            Cz[(size_t)(row0 + 8) * N + col]     = c[mt][nt][2] + b0;
            Cz[(size_t)(row0 + 8) * N + col + 1] = c[mt][nt][3] + b1;
        }
    }
}

// ---------------- fp32 fallback GEMM (t2 only, tiny) ----------------
template<int BM, int BN, int TM, int TN>
__global__ void __launch_bounds__(256)
gemm_nt(const float* __restrict__ A, const float* __restrict__ B,
        const float* __restrict__ bias, float* __restrict__ C,
        int M, int N, int K, int kChunk) {
    constexpr int BK = 8;
    __shared__ float As[BK][BM];
    __shared__ float Bs[BK][BN];
    const int tid = threadIdx.x;
    const int kBase = blockIdx.z * kChunk;
    const float* Ab = A + (size_t)blockIdx.y * BM * K + kBase;
    const float* Bb = B + (size_t)blockIdx.x * BN * K + kBase;
    float acc[TM][TN];
#pragma unroll
    for (int i = 0; i < TM; i++)
#pragma unroll
        for (int j = 0; j < TN; j++) acc[i][j] = 0.f;

    const int tRow = (tid / (BN / TN)) * TM;
    const int tCol = (tid % (BN / TN)) * TN;

    for (int kt = 0; kt < kChunk; kt += BK) {
        for (int i = tid; i < BM * 2; i += 256) {
            int row = i >> 1, c4 = (i & 1) << 2;
            float4 v = *(const float4*)(Ab + (size_t)row * K + kt + c4);
            As[c4 + 0][row] = v.x; As[c4 + 1][row] = v.y;
            As[c4 + 2][row] = v.z; As[c4 + 3][row] = v.w;
        }
        for (int i = tid; i < BN * 2; i += 256) {
            int row = i >> 1, c4 = (i & 1) << 2;
            float4 v = *(const float4*)(Bb + (size_t)row * K + kt + c4);
            Bs[c4 + 0][row] = v.x; Bs[c4 + 1][row] = v.y;
            Bs[c4 + 2][row] = v.z; Bs[c4 + 3][row] = v.w;
        }
        __syncthreads();
#pragma unroll
        for (int k = 0; k < BK; k++) {
            float ra[TM], rb[TN];
#pragma unroll
            for (int i = 0; i < TM; i += 4)
                *(float4*)&ra[i] = *(const float4*)&As[k][tRow + i];
#pragma unroll
            for (int j = 0; j < TN; j += 4)
                *(float4*)&rb[j] = *(const float4*)&Bs[k][tCol + j];
#pragma unroll
            for (int i = 0; i < TM; i++)
#pragma unroll
                for (int j = 0; j < TN; j++)
                    acc[i][j] += ra[i] * rb[j];
        }
        __syncthreads();
    }

    float* Cb = C + (size_t)blockIdx.z * M * N
                  + (size_t)(blockIdx.y * BM + tRow) * N + blockIdx.x * BN + tCol;
    const bool addb = (bias != nullptr) && (blockIdx.z == 0);
#pragma unroll
    for (int i = 0; i < TM; i++)
#pragma unroll
        for (int j = 0; j < TN; j++) {
            float v = acc[i][j];
            if (addb) v += bias[blockIdx.x * BN + tCol + j];
            Cb[(size_t)i * N + j] = v;
        }
}

// ---------------- bilinear-resized position biases ----------------
__global__ void bias_resize_kernel(const float* __restrict__ an, const float* __restrict__ na,
                                   const float* __restrict__ ah, const float* __restrict__ aw,
                                   const float* __restrict__ ha, const float* __restrict__ wa,
                                   float* __restrict__ pb, float* __restrict__ ab) {
    int i = blockIdx.x * 256 + threadIdx.x;
    if (i >= NHD * NAG * NTOK) return;
    int h = i / (NAG * NTOK);
    int rem = i % (NAG * NTOK);
    int a = rem / NTOK;
    int n = rem % NTOK;
    int r = n / 14, c = n % 14;

    auto coord = [](int j, int& i0, int& i1, float& w) {
        float src = (j + 0.5f) * 0.5f - 0.5f;
        src = fmaxf(src, 0.f);
        src = fminf(src, 6.f);
        i0 = (int)floorf(src);
        i1 = min(i0 + 1, 6);
        w = src - (float)i0;
    };
    int r0, r1, c0, c1; float wr, wc;
    coord(r, r0, r1, wr);
    coord(c, c0, c1, wc);

    const float* T1 = an + ((size_t)h * NAG + a) * 49;
    float v1 = (1.f - wr) * ((1.f - wc) * T1[r0 * 7 + c0] + wc * T1[r0 * 7 + c1])
             + wr * ((1.f - wc) * T1[r1 * 7 + c0] + wc * T1[r1 * 7 + c1]);
    pb[((size_t)h * NAG + a) * NTOK + n] =
        v1 + ah[((size_t)h * NAG + a) * 14 + r] + aw[((size_t)h * NAG + a) * 14 + c];

    const float* T2 = na + ((size_t)h * NAG + a) * 49;
    float v2 = (1.f - wr) * ((1.f - wc) * T2[r0 * 7 + c0] + wc * T2[r0 * 7 + c1])
             + wr * ((1.f - wc) * T2[r1 * 7 + c0] + wc * T2[r1 * 7 + c1]);
    ab[((size_t)h * NTOK + n) * NAG + a] =
        v2 + ha[((size_t)h * 14 + r) * NAG + a] + wa[((size_t)h * 14 + c) * NAG + a];
}

// ---------------- agent attention (register softmax) ----------------
__global__ void __launch_bounds__(256)
attn_kernel(const float* __restrict__ qkv, const float* __restrict__ pb,
            const float* __restrict__ ab, float* __restrict__ o_out) {
    __shared__ __align__(16) float qs[1568];
    __shared__ __align__(16) float ks[1568];
    __shared__ __align__(16) float vs[1568];
    __shared__ __align__(16) float ag[392];
    __shared__ __align__(16) float av[392];

    const int b = blockIdx.x >> 3, h = blockIdx.x & 7;
    const int tid = threadIdx.x;
    const float scale = 0.35355339059327373f;
    const float* base = qkv + (size_t)b * NTOK * 192 + h * 8;

    for (int i = tid; i < 392; i += 256) {
        int n = i >> 1, p = (i & 1) << 2;
        *(float4*)&qs[n * 8 + p] = *(const float4*)(base + n * 192 + p);
        *(float4*)&ks[n * 8 + p] = *(const float4*)(base + n * 192 + 64 + p);
        *(float4*)&vs[n * 8 + p] = *(const float4*)(base + n * 192 + 128 + p);
    }
    __syncthreads();

    // agent tokens: 2x2 mean pool of q
    for (int i = tid; i < 98; i += 256) {
        int a = i >> 1, p = (i & 1) << 2;
        int ar = a / 7, ac = a % 7;
        int n0 = ar * 28 + ac * 2;
        float4 v0 = *(float4*)&qs[n0 * 8 + p];
        float4 v1 = *(float4*)&qs[(n0 + 1) * 8 + p];
        float4 v2 = *(float4*)&qs[(n0 + 14) * 8 + p];
        float4 v3 = *(float4*)&qs[(n0 + 15) * 8 + p];
        float4 r;
        r.x = 0.25f * (v0.x + v1.x + v2.x + v3.x);
        r.y = 0.25f * (v0.y + v1.y + v2.y + v3.y);
        r.z = 0.25f * (v0.z + v1.z + v2.z + v3.z);
        r.w = 0.25f * (v0.w + v1.w + v2.w + v3.w);
        *(float4*)&ag[a * 8 + p] = r;
    }
    __syncthreads();

    // stage 1: warp per agent row, rows in registers, agent_v fused
    const int warp = tid >> 5, lane = tid & 31;
    const float* pbh = pb + (size_t)h * NAG * NTOK;
    for (int a = warp; a < NAG; a += 8) {
        float4 g0 = *(float4*)&ag[a * 8];
        float4 g1 = *(float4*)&ag[a * 8 + 4];
        float e[7];
        float m = -1e30f;
#pragma unroll
        for (int i = 0; i < 7; i++) {
            int n = lane + i * 32;
            float s = -1e30f;
            if (n < NTOK) {
                float4 k0 = *(float4*)&ks[n * 8];
                float4 k1 = *(float4*)&ks[n * 8 + 4];
                s = g0.x * k0.x + g0.y * k0.y + g0.z * k0.z + g0.w * k0.w
                  + g1.x * k1.x + g1.y * k1.y + g1.z * k1.z + g1.w * k1.w;
                s = s * scale + pbh[a * NTOK + n];
            }
            e[i] = s;
            m = fmaxf(m, s);
        }
#pragma unroll
        for (int o = 16; o; o >>= 1) m = fmaxf(m, __shfl_xor_sync(0xffffffffu, m, o));
        float sum = 0.f;
        float4 a0 = {0, 0, 0, 0}, a1 = {0, 0, 0, 0};
#pragma unroll
        for (int i = 0; i < 7; i++) {
            int n = lane + i * 32;
            if (n < NTOK) {
                float p = __expf(e[i] - m);
                sum += p;
                float4 v0 = *(float4*)&vs[n * 8];
                float4 v1 = *(float4*)&vs[n * 8 + 4];
                a0.x += p * v0.x; a0.y += p * v0.y; a0.z += p * v0.z; a0.w += p * v0.w;
                a1.x += p * v1.x; a1.y += p * v1.y; a1.z += p * v1.z; a1.w += p * v1.w;
            }
        }
#pragma unroll
        for (int o = 16; o; o >>= 1) {
            sum  += __shfl_xor_sync(0xffffffffu, sum, o);
            a0.x += __shfl_xor_sync(0xffffffffu, a0.x, o);
            a0.y += __shfl_xor_sync(0xffffffffu, a0.y, o);
            a0.z += __shfl_xor_sync(0xffffffffu, a0.z, o);
            a0.w += __shfl_xor_sync(0xffffffffu, a0.w, o);
            a1.x += __shfl_xor_sync(0xffffffffu, a1.x, o);
            a1.y += __shfl_xor_sync(0xffffffffu, a1.y, o);
            a1.z += __shfl_xor_sync(0xffffffffu, a1.z, o);
            a1.w += __shfl_xor_sync(0xffffffffu, a1.w, o);
        }
        if (lane == 0) {
            float inv = 1.f / sum;
            av[a * 8 + 0] = a0.x * inv; av[a * 8 + 1] = a0.y * inv;
            av[a * 8 + 2] = a0.z * inv; av[a * 8 + 3] = a0.w * inv;
            av[a * 8 + 4] = a1.x * inv; av[a * 8 + 5] = a1.y * inv;
            av[a * 8 + 6] = a1.z * inv; av[a * 8 + 7] = a1.w * inv;
        }
    }
    __syncthreads();

    // stage 2: thread per token, two-pass softmax (no row array)
    if (tid < NTOK) {
        const int n = tid;
        const float* abh = ab + (size_t)h * NTOK * NAG + n * NAG;
        float4 q0 = *(float4*)&qs[n * 8];
        float4 q1 = *(float4*)&qs[n * 8 + 4];
        q0.x *= scale; q0.y *= scale; q0.z *= scale; q0.w *= scale;
        q1.x *= scale; q1.y *= scale; q1.z *= scale; q1.w *= scale;
        float m = -1e30f;
#pragma unroll
        for (int a = 0; a < NAG; a++) {
            float4 g0 = *(float4*)&ag[a * 8];
            float4 g1 = *(float4*)&ag[a * 8 + 4];
            float s = q0.x * g0.x + q0.y * g0.y + q0.z * g0.z + q0.w * g0.w
                    + q1.x * g1.x + q1.y * g1.y + q1.z * g1.z + q1.w * g1.w + abh[a];
            m = fmaxf(m, s);
        }
        float sum = 0.f;
        float4 o0 = {0, 0, 0, 0}, o1 = {0, 0, 0, 0};
#pragma unroll
        for (int a = 0; a < NAG; a++) {
            float4 g0 = *(float4*)&ag[a * 8];
            float4 g1 = *(float4*)&ag[a * 8 + 4];
            float s = q0.x * g0.x + q0.y * g0.y + q0.z * g0.z + q0.w * g0.w
                    + q1.x * g1.x + q1.y * g1.y + q1.z * g1.z + q1.w * g1.w + abh[a];
            float p = __expf(s - m);
            sum += p;
            float4 w0 = *(float4*)&av[a * 8];
            float4 w1 = *(float4*)&av[a * 8 + 4];
            o0.x += p * w0.x; o0.y += p * w0.y; o0.z += p * w0.z; o0.w += p * w0.w;
            o1.x += p * w1.x; o1.y += p * w1.y; o1.z += p * w1.z; o1.w += p * w1.w;
        }
        float inv = 1.f / sum;
        o0.x *= inv; o0.y *= inv; o0.z *= inv; o0.w *= inv;
        o1.x *= inv; o1.y *= inv; o1.z *= inv; o1.w *= inv;
        float* ob = o_out + (size_t)b * 12544 + n * 64 + h * 8;
        *(float4*)(ob) = o0;
        *(float4*)(ob + 4) = o1;
    }
}

// ---------------- depthwise 3x3 conv on v + residual add ----------------
__global__ void __launch_bounds__(256)
dwc_kernel(const float* __restrict__ qkv, const float* __restrict__ o_in,
           const float* __restrict__ dwc_w, const float* __restrict__ dwc_b,
           float* __restrict__ t_out) {
    extern __shared__ float vsm[];
    const int b = blockIdx.x, tid = threadIdx.x;
    const float* base = qkv + (size_t)b * NTOK * 192 + 128;
    for (int i = tid; i < 12544; i += 256) {
        int n = i >> 6, c = i & 63;
        vsm[i] = base[n * 192 + c];
    }
    __syncthreads();
    const float* ob = o_in + (size_t)b * 12544;
    float* tb = t_out + (size_t)b * 12544;
    for (int i = tid; i < 12544; i += 256) {
        int n = i >> 6, c = i & 63;
        int r = n / 14, col = n % 14;
        float acc = ob[i] + dwc_b[c];
#pragma unroll
        for (int dr = -1; dr <= 1; dr++) {
            int rr = r + dr;
            if (rr < 0 || rr > 13) continue;
#pragma unroll
            for (int dc = -1; dc <= 1; dc++) {
                int cc = col + dc;
                if (cc < 0 || cc > 13) continue;
                acc += dwc_w[c * 9 + (dr + 1) * 3 + (dc + 1)] * vsm[(rr * 14 + cc) * 64 + c];
            }
        }
        tb[i] = acc;
    }
}

// ---------------- split-K reduces ----------------
__global__ void reduce_adj(const float* __restrict__ part, float* __restrict__ out) {
    int i = blockIdx.x * 256 + threadIdx.x;
    if (i >= 768 * 256) return;
    float s = 0.f;
#pragma unroll
    for (int z = 0; z < 14; z++) s += part[(size_t)z * 768 * 256 + i];
    out[i] = s;
}

__global__ void reduce_tanh(const float* __restrict__ part, float* __restrict__ hbuf) {
    int i = blockIdx.x * 256 + threadIdx.x;
    if (i >= 768 * 256) return;
    float s = 0.f;
#pragma unroll
    for (int z = 0; z < 8; z++) s += part[(size_t)z * 768 * 256 + i];
    hbuf[i] = tanhf(s);
}

__global__ void reduce_t2(const float* __restrict__ part, float* __restrict__ dout) {
    int i = blockIdx.x * 256 + threadIdx.x;
    if (i >= 768 * 128) return;
    float s = 0.f;
#pragma unroll
    for (int z = 0; z < 4; z++) s += part[(size_t)z * 768 * 128 + i];
    int r = i >> 7, j = i & 127;
    int b = r / 3, which = r % 3;
    dout[(size_t)which * 32768 + b * 128 + j] = s;
}

// ---------------- launch ----------------
extern "C" void kernel_launch(void* const* d_in, const int* in_sizes, int n_in,
                              void* d_out, int out_size) {
    (void)in_sizes; (void)n_in; (void)out_size;
    const float* X       = (const float*)d_in[0];
    const float* W_embed = (const float*)d_in[1];
    const float* b_embed = (const float*)d_in[2];
    const float* W_qkv   = (const float*)d_in[3];
    const float* W_proj  = (const float*)d_in[4];
    const float* b_proj  = (const float*)d_in[5];
    const float* dwc_w   = (const float*)d_in[6];
    const float* dwc_b   = (const float*)d_in[7];
    const float* an_bias = (const float*)d_in[8];
    const float* na_bias = (const float*)d_in[9];
    const float* ah_bias = (const float*)d_in[10];
    const float* aw_bias = (const float*)d_in[11];
    const float* ha_bias = (const float*)d_in[12];
    const float* wa_bias = (const float*)d_in[13];
    const float* W_adj   = (const float*)d_in[14];
    const float* b_adj   = (const float*)d_in[15];
    const float* W_t1    = (const float*)d_in[16];
    const float* b_t1    = (const float*)d_in[17];
    const float* W_t2    = (const float*)d_in[18];
    const float* b_t2    = (const float*)d_in[19];
    float* out = (float*)d_out;

    float* ws = nullptr;
    cudaGetSymbolAddress((void**)&ws, g_ws);
    float* xt    = ws + OFF_XT;
    float* qkv   = ws + OFF_QKV;
    float* obuf  = ws + OFF_O;
    float* tbuf  = ws + OFF_T;
    float* oproj = ws + OFF_OPROJ;
    float* pb    = ws + OFF_PB;
    float* ab    = ws + OFF_AB;
    float* hbuf  = ws + OFF_H;
    float* scr   = ws + OFF_SCR;

    const int DWC_SMEM = 12544 * 4;
    cudaFuncSetAttribute(dwc_kernel, cudaFuncAttributeMaxDynamicSharedMemorySize, DWC_SMEM);

    bias_resize_kernel<<<(NHD * NAG * NTOK + 255) / 256, 256>>>(
        an_bias, na_bias, ah_bias, aw_bias, ha_bias, wa_bias, pb, ab);

    // embed: (768,1280) x (12544,1280)^T + b -> xt   [tf32 TC]
    gemm_tf32<128, 128, 64, 32><<<dim3(98, 6, 1), 256>>>(
        X, W_embed, b_embed, xt, 768, 12544, 1280, 1280);

    // qkv: (150528,64) x (192,64)^T -> qkv   [tf32 TC]
    gemm_tf32<128, 64, 32, 32><<<dim3(3, 1176, 1), 256>>>(
        xt, W_qkv, nullptr, qkv, 150528, 192, 64, 64);

    // agent attention
    attn_kernel<<<B3 * NHD, 256>>>(qkv, pb, ab, obuf);

    // dwc + residual -> tbuf
    dwc_kernel<<<B3, 256, DWC_SMEM>>>(qkv, obuf, dwc_w, dwc_b, tbuf);

    // proj: (150528,64) x (64,64)^T + b -> oproj   [tf32 TC]
    gemm_tf32<128, 64, 32, 32><<<dim3(1, 1176, 1), 256>>>(
        tbuf, W_proj, b_proj, oproj, 150528, 64, 64, 64);

    // adj: (768,12544) x (256,12544)^T + b, split 14 -> scr -> X_adj
    gemm_tf32<128, 128, 64, 32><<<dim3(2, 6, 14), 256>>>(
        oproj, W_adj, b_adj, scr, 768, 256, 12544, 896);
    reduce_adj<<<768, 256>>>(scr, out + 98304);

    // MLP t1: (768,1280) x (256,1280)^T + b, split 8, tanh -> hbuf
    gemm_tf32<128, 128, 64, 32><<<dim3(2, 6, 8), 256>>>(
        X, W_t1, b_t1, scr, 768, 256, 1280, 160);
    reduce_tanh<<<768, 256>>>(scr, hbuf);

    // MLP t2: (768,256) x (128,256)^T + b, split 4 -> anchor/pos/neg
    gemm_nt<128, 64, 8, 4><<<dim3(2, 6, 4), 256>>>(
        hbuf, W_t2, b_t2, scr, 768, 128, 256, 64);
    reduce_t2<<<(768 * 128 + 255) / 256, 256>>>(scr, out);
}

// round 7
// speedup vs baseline: 1.8716x; 1.0704x over previous
#include <cuda_runtime.h>
#include <stdint.h>
#include <math.h>

// ---------------- sizes ----------------
// B=256, b3=768, D=1280, C=64, WIN=14, N=196, NH=8, HD=8, A=49
#define B3    768
#define NTOK  196
#define NHD   8
#define NAG   49

constexpr size_t SZ_XT    = 768ull * 12544;
constexpr size_t SZ_QKV   = 768ull * 196 * 192;
constexpr size_t SZ_T     = 768ull * 12544;
constexpr size_t SZ_OPROJ = 768ull * 12544;
constexpr size_t SZ_PB    = 8ull * 49 * 196;
constexpr size_t SZ_AB    = 8ull * 196 * 49;
constexpr size_t SZ_H     = 768ull * 256;
constexpr size_t SZ_SCR   = 16ull * 768 * 256;

constexpr size_t OFF_XT    = 0;
constexpr size_t OFF_QKV   = OFF_XT + SZ_XT;
constexpr size_t OFF_T     = OFF_QKV + SZ_QKV;
constexpr size_t OFF_OPROJ = OFF_T + SZ_T;
constexpr size_t OFF_PB    = OFF_OPROJ + SZ_OPROJ;
constexpr size_t OFF_AB    = OFF_PB + SZ_PB;
constexpr size_t OFF_H     = OFF_AB + SZ_AB;
constexpr size_t OFF_SCR   = OFF_H + SZ_H;
constexpr size_t WS_TOTAL  = OFF_SCR + SZ_SCR;

__device__ __align__(256) float g_ws[WS_TOTAL];

__device__ __forceinline__ uint32_t f2tf32(float x) {
    uint32_t u;
    asm("cvt.rna.tf32.f32 %0, %1;" : "=r"(u) : "f"(x));
    return u;
}

// ---------------- tf32 tensor-core NT GEMM ----------------
template<int BM, int BN, int WM, int WN>
__global__ void __launch_bounds__(256)
gemm_tf32(const float* __restrict__ A, const float* __restrict__ B,
          const float* __restrict__ bias, float* __restrict__ C,
          int M, int N, int K, int kChunk) {
    constexpr int BK = 32;
    constexpr int WARPS_N = BN / WN;
    constexpr int MT = WM / 16;
    constexpr int NT = WN / 8;
    constexpr int LDA = BM + 4;
    constexpr int LDB = BN + 4;
    constexpr int A_ITERS = BM * BK / 1024;
    constexpr int B_ITERS = BN * BK / 1024;

    __shared__ float As[BK][LDA];
    __shared__ float Bs[BK][LDB];

    const int tid = threadIdx.x;
    const int lane = tid & 31;
    const int warp = tid >> 5;
    const int wr = (warp / WARPS_N) * WM;
    const int wc = (warp % WARPS_N) * WN;
    const int gid = lane >> 2;
    const int tg  = lane & 3;

    const int kBase = blockIdx.z * kChunk;
    const float* Ab = A + (size_t)blockIdx.y * BM * K + kBase;
    const float* Bb = B + (size_t)blockIdx.x * BN * K + kBase;

    float c[MT][NT][4];
#pragma unroll
    for (int i = 0; i < MT; i++)
#pragma unroll
        for (int j = 0; j < NT; j++)
#pragma unroll
            for (int r = 0; r < 4; r++) c[i][j][r] = 0.f;

    for (int kt = 0; kt < kChunk; kt += BK) {
#pragma unroll
        for (int it = 0; it < A_ITERS; it++) {
            int linear = tid + it * 256;
            int row = linear >> 3;
            int cv = (linear & 7) << 2;
            float4 v = *(const float4*)(Ab + (size_t)row * K + kt + cv);
            As[cv + 0][row] = __uint_as_float(f2tf32(v.x));
            As[cv + 1][row] = __uint_as_float(f2tf32(v.y));
            As[cv + 2][row] = __uint_as_float(f2tf32(v.z));
            As[cv + 3][row] = __uint_as_float(f2tf32(v.w));
        }
#pragma unroll
        for (int it = 0; it < B_ITERS; it++) {
            int linear = tid + it * 256;
            int row = linear >> 3;
            int cv = (linear & 7) << 2;
            float4 v = *(const float4*)(Bb + (size_t)row * K + kt + cv);
            Bs[cv + 0][row] = __uint_as_float(f2tf32(v.x));
            Bs[cv + 1][row] = __uint_as_float(f2tf32(v.y));
            Bs[cv + 2][row] = __uint_as_float(f2tf32(v.z));
            Bs[cv + 3][row] = __uint_as_float(f2tf32(v.w));
        }
        __syncthreads();

#pragma unroll
        for (int kk = 0; kk < 4; kk++) {
            uint32_t af[MT][4];
            uint32_t bf[NT][2];
#pragma unroll
            for (int mt = 0; mt < MT; mt++) {
                af[mt][0] = __float_as_uint(As[kk * 8 + tg][wr + mt * 16 + gid]);
                af[mt][1] = __float_as_uint(As[kk * 8 + tg][wr + mt * 16 + gid + 8]);
                af[mt][2] = __float_as_uint(As[kk * 8 + tg + 4][wr + mt * 16 + gid]);
                af[mt][3] = __float_as_uint(As[kk * 8 + tg + 4][wr + mt * 16 + gid + 8]);
            }
#pragma unroll
            for (int nt = 0; nt < NT; nt++) {
                bf[nt][0] = __float_as_uint(Bs[kk * 8 + tg][wc + nt * 8 + gid]);
                bf[nt][1] = __float_as_uint(Bs[kk * 8 + tg + 4][wc + nt * 8 + gid]);
            }
#pragma unroll
            for (int mt = 0; mt < MT; mt++)
#pragma unroll
                for (int nt = 0; nt < NT; nt++) {
                    asm volatile(
                        "mma.sync.aligned.m16n8k8.row.col.f32.tf32.tf32.f32 "
                        "{%0,%1,%2,%3}, {%4,%5,%6,%7}, {%8,%9}, {%0,%1,%2,%3};\n"
                        : "+f"(c[mt][nt][0]), "+f"(c[mt][nt][1]),
                          "+f"(c[mt][nt][2]), "+f"(c[mt][nt][3])
                        : "r"(af[mt][0]), "r"(af[mt][1]), "r"(af[mt][2]), "r"(af[mt][3]),
                          "r"(bf[nt][0]), "r"(bf[nt][1]));
                }
        }
        __syncthreads();
    }

    const bool addb = (bias != nullptr) && (blockIdx.z == 0);
    float* Cz = C + (size_t)blockIdx.z * M * N;
#pragma unroll
    for (int mt = 0; mt < MT; mt++) {
        int row0 = blockIdx.y * BM + wr + mt * 16 + gid;
#pragma unroll
        for (int nt = 0; nt < NT; nt++) {
            int col = blockIdx.x * BN + wc + nt * 8 + tg * 2;
            float b0 = addb ? bias[col] : 0.f;
            float b1 = addb ? bias[col + 1] : 0.f;
            Cz[(size_t)row0 * N + col]           = c[mt][nt][0] + b0;
            Cz[(size_t)row0 * N + col + 1]       = c[mt][nt][1] + b1;
            Cz[(size_t)(row0 + 8) * N + col]     = c[mt][nt][2] + b0;
            Cz[(size_t)(row0 + 8) * N + col + 1] = c[mt][nt][3] + b1;
        }
    }
}

// ---------------- fp32 fallback GEMM (t2 only, tiny) ----------------
template<int BM, int BN, int TM, int TN>
__global__ void __launch_bounds__(256)
gemm_nt(const float* __restrict__ A, const float* __restrict__ B,
        const float* __restrict__ bias, float* __restrict__ C,
        int M, int N, int K, int kChunk) {
    constexpr int BK = 8;
    __shared__ float As[BK][BM];
    __shared__ float Bs[BK][BN];
    const int tid = threadIdx.x;
    const int kBase = blockIdx.z * kChunk;
    const float* Ab = A + (size_t)blockIdx.y * BM * K + kBase;
    const float* Bb = B + (size_t)blockIdx.x * BN * K + kBase;
    float acc[TM][TN];
#pragma unroll
    for (int i = 0; i < TM; i++)
#pragma unroll
        for (int j = 0; j < TN; j++) acc[i][j] = 0.f;

    const int tRow = (tid / (BN / TN)) * TM;
    const int tCol = (tid % (BN / TN)) * TN;

    for (int kt = 0; kt < kChunk; kt += BK) {
        for (int i = tid; i < BM * 2; i += 256) {
            int row = i >> 1, c4 = (i & 1) << 2;
            float4 v = *(const float4*)(Ab + (size_t)row * K + kt + c4);
            As[c4 + 0][row] = v.x; As[c4 + 1][row] = v.y;
            As[c4 + 2][row] = v.z; As[c4 + 3][row] = v.w;
        }
        for (int i = tid; i < BN * 2; i += 256) {
            int row = i >> 1, c4 = (i & 1) << 2;
            float4 v = *(const float4*)(Bb + (size_t)row * K + kt + c4);
            Bs[c4 + 0][row] = v.x; Bs[c4 + 1][row] = v.y;
            Bs[c4 + 2][row] = v.z; Bs[c4 + 3][row] = v.w;
        }
        __syncthreads();
#pragma unroll
        for (int k = 0; k < BK; k++) {
            float ra[TM], rb[TN];
#pragma unroll
            for (int i = 0; i < TM; i += 4)
                *(float4*)&ra[i] = *(const float4*)&As[k][tRow + i];
#pragma unroll
            for (int j = 0; j < TN; j += 4)
                *(float4*)&rb[j] = *(const float4*)&Bs[k][tCol + j];
#pragma unroll
            for (int i = 0; i < TM; i++)
#pragma unroll
                for (int j = 0; j < TN; j++)
                    acc[i][j] += ra[i] * rb[j];
        }
        __syncthreads();
    }

    float* Cb = C + (size_t)blockIdx.z * M * N
                  + (size_t)(blockIdx.y * BM + tRow) * N + blockIdx.x * BN + tCol;
    const bool addb = (bias != nullptr) && (blockIdx.z == 0);
#pragma unroll
    for (int i = 0; i < TM; i++)
#pragma unroll
        for (int j = 0; j < TN; j++) {
            float v = acc[i][j];
            if (addb) v += bias[blockIdx.x * BN + tCol + j];
            Cb[(size_t)i * N + j] = v;
        }
}

// ---------------- bilinear-resized position biases ----------------
__global__ void bias_resize_kernel(const float* __restrict__ an, const float* __restrict__ na,
                                   const float* __restrict__ ah, const float* __restrict__ aw,
                                   const float* __restrict__ ha, const float* __restrict__ wa,
                                   float* __restrict__ pb, float* __restrict__ ab) {
    int i = blockIdx.x * 256 + threadIdx.x;
    if (i >= NHD * NAG * NTOK) return;
    int h = i / (NAG * NTOK);
    int rem = i % (NAG * NTOK);
    int a = rem / NTOK;
    int n = rem % NTOK;
    int r = n / 14, c = n % 14;

    auto coord = [](int j, int& i0, int& i1, float& w) {
        float src = (j + 0.5f) * 0.5f - 0.5f;
        src = fmaxf(src, 0.f);
        src = fminf(src, 6.f);
        i0 = (int)floorf(src);
        i1 = min(i0 + 1, 6);
        w = src - (float)i0;
    };
    int r0, r1, c0, c1; float wr, wc;
    coord(r, r0, r1, wr);
    coord(c, c0, c1, wc);

    const float* T1 = an + ((size_t)h * NAG + a) * 49;
    float v1 = (1.f - wr) * ((1.f - wc) * T1[r0 * 7 + c0] + wc * T1[r0 * 7 + c1])
             + wr * ((1.f - wc) * T1[r1 * 7 + c0] + wc * T1[r1 * 7 + c1]);
    pb[((size_t)h * NAG + a) * NTOK + n] =
        v1 + ah[((size_t)h * NAG + a) * 14 + r] + aw[((size_t)h * NAG + a) * 14 + c];

    const float* T2 = na + ((size_t)h * NAG + a) * 49;
    float v2 = (1.f - wr) * ((1.f - wc) * T2[r0 * 7 + c0] + wc * T2[r0 * 7 + c1])
             + wr * ((1.f - wc) * T2[r1 * 7 + c0] + wc * T2[r1 * 7 + c1]);
    ab[((size_t)h * NTOK + n) * NAG + a] =
        v2 + ha[((size_t)h * 14 + r) * NAG + a] + wa[((size_t)h * 14 + c) * NAG + a];
}

// ---------------- fused agent attention + depthwise conv ----------------
// one block per (b, h); smem d-major [8][200] -> conflict-free scalar LDS.
#define LDT 200
__global__ void __launch_bounds__(256)
attn_dwc_kernel(const float* __restrict__ qkv, const float* __restrict__ pb,
                const float* __restrict__ ab, const float* __restrict__ dwc_w,
                const float* __restrict__ dwc_b, float* __restrict__ t_out) {
    __shared__ float qt[8][LDT];
    __shared__ float kt[8][LDT];
    __shared__ float vt[8][LDT];
    __shared__ __align__(16) float ag[392];
    __shared__ __align__(16) float av[392];
    __shared__ float wsm[72];
    __shared__ float bsm[8];

    const int b = blockIdx.x >> 3, h = blockIdx.x & 7;
    const int tid = threadIdx.x;
    const float scale = 0.35355339059327373f;
    const float* base = qkv + (size_t)b * NTOK * 192 + h * 8;

    // load q/k/v transposed into d-major smem
    for (int i = tid; i < 392; i += 256) {
        int n = i >> 1, p = (i & 1) << 2;
        float4 q4 = *(const float4*)(base + n * 192 + p);
        float4 k4 = *(const float4*)(base + n * 192 + 64 + p);
        float4 v4 = *(const float4*)(base + n * 192 + 128 + p);
        qt[p + 0][n] = q4.x; qt[p + 1][n] = q4.y; qt[p + 2][n] = q4.z; qt[p + 3][n] = q4.w;
        kt[p + 0][n] = k4.x; kt[p + 1][n] = k4.y; kt[p + 2][n] = k4.z; kt[p + 3][n] = k4.w;
        vt[p + 0][n] = v4.x; vt[p + 1][n] = v4.y; vt[p + 2][n] = v4.z; vt[p + 3][n] = v4.w;
    }
    if (tid < 72) wsm[tid] = dwc_w[h * 72 + tid];
    if (tid >= 72 && tid < 80) bsm[tid - 72] = dwc_b[h * 8 + tid - 72];
    __syncthreads();

    // agent tokens: 2x2 mean pool of q
    for (int i = tid; i < 392; i += 256) {
        int a = i >> 3, d = i & 7;
        int ar = a / 7, ac = a % 7;
        int n0 = ar * 28 + ac * 2;
        ag[a * 8 + d] = 0.25f * (qt[d][n0] + qt[d][n0 + 1] + qt[d][n0 + 14] + qt[d][n0 + 15]);
    }
    __syncthreads();

    // stage 1: warp per agent row; fused softmax + agent_v
    const int warp = tid >> 5, lane = tid & 31;
    const float* pbh = pb + (size_t)h * NAG * NTOK;
    for (int a = warp; a < NAG; a += 8) {
        float g[8];
#pragma unroll
        for (int d = 0; d < 8; d++) g[d] = ag[a * 8 + d];   // broadcast
        float e[7];
        float m = -1e30f;
#pragma unroll
        for (int i = 0; i < 7; i++) {
            int n = lane + i * 32;
            float s = -1e30f;
            if (n < NTOK) {
                s = g[0] * kt[0][n] + g[1] * kt[1][n] + g[2] * kt[2][n] + g[3] * kt[3][n]
                  + g[4] * kt[4][n] + g[5] * kt[5][n] + g[6] * kt[6][n] + g[7] * kt[7][n];
                s = s * scale + pbh[a * NTOK + n];
            }
            e[i] = s;
            m = fmaxf(m, s);
        }
#pragma unroll
        for (int o = 16; o; o >>= 1) m = fmaxf(m, __shfl_xor_sync(0xffffffffu, m, o));
        float sum = 0.f;
        float acc[8];
#pragma unroll
        for (int d = 0; d < 8; d++) acc[d] = 0.f;
#pragma unroll
        for (int i = 0; i < 7; i++) {
            int n = lane + i * 32;
            if (n < NTOK) {
                float p = __expf(e[i] - m);
                sum += p;
#pragma unroll
                for (int d = 0; d < 8; d++) acc[d] += p * vt[d][n];
            }
        }
#pragma unroll
        for (int o = 16; o; o >>= 1) {
            sum += __shfl_xor_sync(0xffffffffu, sum, o);
#pragma unroll
            for (int d = 0; d < 8; d++) acc[d] += __shfl_xor_sync(0xffffffffu, acc[d], o);
        }
        if (lane == 0) {
            float inv = 1.f / sum;
#pragma unroll
            for (int d = 0; d < 8; d++) av[a * 8 + d] = acc[d] * inv;
        }
    }
    __syncthreads();

    // stage 2 + dwc: thread per token
    if (tid < NTOK) {
        const int n = tid;
        const float* abh = ab + (size_t)h * NTOK * NAG + n * NAG;
        float q[8];
#pragma unroll
        for (int d = 0; d < 8; d++) q[d] = qt[d][n] * scale;   // conflict-free
        float m = -1e30f;
#pragma unroll 7
        for (int a = 0; a < NAG; a++) {
            const float* g = &ag[a * 8];
            float s = q[0] * g[0] + q[1] * g[1] + q[2] * g[2] + q[3] * g[3]
                    + q[4] * g[4] + q[5] * g[5] + q[6] * g[6] + q[7] * g[7] + abh[a];
            m = fmaxf(m, s);
        }
        float sum = 0.f;
        float o[8];
#pragma unroll
        for (int d = 0; d < 8; d++) o[d] = 0.f;
#pragma unroll 7
        for (int a = 0; a < NAG; a++) {
            const float* g = &ag[a * 8];
            float s = q[0] * g[0] + q[1] * g[1] + q[2] * g[2] + q[3] * g[3]
                    + q[4] * g[4] + q[5] * g[5] + q[6] * g[6] + q[7] * g[7] + abh[a];
            float p = __expf(s - m);
            sum += p;
            const float* w = &av[a * 8];
#pragma unroll
            for (int d = 0; d < 8; d++) o[d] += p * w[d];
        }
        float inv = 1.f / sum;

        // depthwise 3x3 conv on v (channel c = h*8+d) + residual
        const int r = n / 14, col = n % 14;
        float res[8];
#pragma unroll
        for (int d = 0; d < 8; d++) res[d] = o[d] * inv + bsm[d];
#pragma unroll
        for (int dr = -1; dr <= 1; dr++) {
            int rr = r + dr;
            if (rr < 0 || rr > 13) continue;
#pragma unroll
            for (int dc = -1; dc <= 1; dc++) {
                int cc = col + dc;
                if (cc < 0 || cc > 13) continue;
                int nn = rr * 14 + cc;
                int kk = (dr + 1) * 3 + (dc + 1);
#pragma unroll
                for (int d = 0; d < 8; d++) res[d] += wsm[d * 9 + kk] * vt[d][nn];
            }
        }
        float* tb = t_out + (size_t)b * 12544 + n * 64 + h * 8;
        float4 r0 = {res[0], res[1], res[2], res[3]};
        float4 r1 = {res[4], res[5], res[6], res[7]};
        *(float4*)tb = r0;
        *(float4*)(tb + 4) = r1;
    }
}

// ---------------- split-K reduces ----------------
__global__ void reduce_adj(const float* __restrict__ part, float* __restrict__ out) {
    int i = blockIdx.x * 256 + threadIdx.x;
    if (i >= 768 * 256) return;
    float s = 0.f;
#pragma unroll
    for (int z = 0; z < 14; z++) s += part[(size_t)z * 768 * 256 + i];
    out[i] = s;
}

__global__ void reduce_tanh(const float* __restrict__ part, float* __restrict__ hbuf) {
    int i = blockIdx.x * 256 + threadIdx.x;
    if (i >= 768 * 256) return;
    float s = 0.f;
#pragma unroll
    for (int z = 0; z < 8; z++) s += part[(size_t)z * 768 * 256 + i];
    hbuf[i] = tanhf(s);
}

__global__ void reduce_t2(const float* __restrict__ part, float* __restrict__ dout) {
    int i = blockIdx.x * 256 + threadIdx.x;
    if (i >= 768 * 128) return;
    float s = 0.f;
#pragma unroll
    for (int z = 0; z < 4; z++) s += part[(size_t)z * 768 * 128 + i];
    int r = i >> 7, j = i & 127;
    int b = r / 3, which = r % 3;
    dout[(size_t)which * 32768 + b * 128 + j] = s;
}

// ---------------- launch ----------------
extern "C" void kernel_launch(void* const* d_in, const int* in_sizes, int n_in,
                              void* d_out, int out_size) {
    (void)in_sizes; (void)n_in; (void)out_size;
    const float* X       = (const float*)d_in[0];
    const float* W_embed = (const float*)d_in[1];
    const float* b_embed = (const float*)d_in[2];
    const float* W_qkv   = (const float*)d_in[3];
    const float* W_proj  = (const float*)d_in[4];
    const float* b_proj  = (const float*)d_in[5];
    const float* dwc_w   = (const float*)d_in[6];
    const float* dwc_b   = (const float*)d_in[7];
    const float* an_bias = (const float*)d_in[8];
    const float* na_bias = (const float*)d_in[9];
    const float* ah_bias = (const float*)d_in[10];
    const float* aw_bias = (const float*)d_in[11];
    const float* ha_bias = (const float*)d_in[12];
    const float* wa_bias = (const float*)d_in[13];
    const float* W_adj   = (const float*)d_in[14];
    const float* b_adj   = (const float*)d_in[15];
    const float* W_t1    = (const float*)d_in[16];
    const float* b_t1    = (const float*)d_in[17];
    const float* W_t2    = (const float*)d_in[18];
    const float* b_t2    = (const float*)d_in[19];
    float* out = (float*)d_out;

    float* ws = nullptr;
    cudaGetSymbolAddress((void**)&ws, g_ws);
    float* xt    = ws + OFF_XT;
    float* qkv   = ws + OFF_QKV;
    float* tbuf  = ws + OFF_T;
    float* oproj = ws + OFF_OPROJ;
    float* pb    = ws + OFF_PB;
    float* ab    = ws + OFF_AB;
    float* hbuf  = ws + OFF_H;
    float* scr   = ws + OFF_SCR;

    bias_resize_kernel<<<(NHD * NAG * NTOK + 255) / 256, 256>>>(
        an_bias, na_bias, ah_bias, aw_bias, ha_bias, wa_bias, pb, ab);

    // embed: (768,1280) x (12544,1280)^T + b -> xt   [tf32 TC]
    gemm_tf32<128, 128, 64, 32><<<dim3(98, 6, 1), 256>>>(
        X, W_embed, b_embed, xt, 768, 12544, 1280, 1280);

    // qkv: (150528,64) x (192,64)^T -> qkv   [tf32 TC]
    gemm_tf32<128, 64, 32, 32><<<dim3(3, 1176, 1), 256>>>(
        xt, W_qkv, nullptr, qkv, 150528, 192, 64, 64);

    // fused agent attention + dwc -> tbuf
    attn_dwc_kernel<<<B3 * NHD, 256>>>(qkv, pb, ab, dwc_w, dwc_b, tbuf);

    // proj: (150528,64) x (64,64)^T + b -> oproj   [tf32 TC]
    gemm_tf32<128, 64, 32, 32><<<dim3(1, 1176, 1), 256>>>(
        tbuf, W_proj, b_proj, oproj, 150528, 64, 64, 64);

    // adj: (768,12544) x (256,12544)^T + b, split 14 -> scr -> X_adj
    gemm_tf32<128, 128, 64, 32><<<dim3(2, 6, 14), 256>>>(
        oproj, W_adj, b_adj, scr, 768, 256, 12544, 896);
    reduce_adj<<<768, 256>>>(scr, out + 98304);

    // MLP t1: (768,1280) x (256,1280)^T + b, split 8, tanh -> hbuf
    gemm_tf32<128, 128, 64, 32><<<dim3(2, 6, 8), 256>>>(
        X, W_t1, b_t1, scr, 768, 256, 1280, 160);
    reduce_tanh<<<768, 256>>>(scr, hbuf);

    // MLP t2: (768,256) x (128,256)^T + b, split 4 -> anchor/pos/neg
    gemm_nt<128, 64, 8, 4><<<dim3(2, 6, 4), 256>>>(
        hbuf, W_t2, b_t2, scr, 768, 128, 256, 64);
    reduce_t2<<<(768 * 128 + 255) / 256, 256>>>(scr, out);
}

// round 8
// speedup vs baseline: 2.5975x; 1.3878x over previous
#include <cuda_runtime.h>
#include <stdint.h>
#include <math.h>

// ---------------- sizes ----------------
// B=256, b3=768, D=1280, C=64, WIN=14, N=196, NH=8, HD=8, A=49
#define B3    768
#define NTOK  196
#define NHD   8
#define NAG   49

constexpr size_t SZ_XT    = 768ull * 12544;
constexpr size_t SZ_QKV   = 768ull * 196 * 192;
constexpr size_t SZ_T     = 768ull * 12544;
constexpr size_t SZ_OPROJ = 768ull * 12544;
constexpr size_t SZ_PB    = 8ull * 49 * 196;
constexpr size_t SZ_AB    = 8ull * 49 * 196;
constexpr size_t SZ_H     = 768ull * 256;
constexpr size_t SZ_SCR   = 16ull * 768 * 256;

constexpr size_t OFF_XT    = 0;
constexpr size_t OFF_QKV   = OFF_XT + SZ_XT;
constexpr size_t OFF_T     = OFF_QKV + SZ_QKV;
constexpr size_t OFF_OPROJ = OFF_T + SZ_T;
constexpr size_t OFF_PB    = OFF_OPROJ + SZ_OPROJ;
constexpr size_t OFF_AB    = OFF_PB + SZ_PB;
constexpr size_t OFF_H     = OFF_AB + SZ_AB;
constexpr size_t OFF_SCR   = OFF_H + SZ_H;
constexpr size_t WS_TOTAL  = OFF_SCR + SZ_SCR;

__device__ __align__(256) float g_ws[WS_TOTAL];

__device__ __forceinline__ uint32_t f2tf32(float x) {
    uint32_t u;
    asm("cvt.rna.tf32.f32 %0, %1;" : "=r"(u) : "f"(x));
    return u;
}

// ---------------- tf32 tensor-core NT GEMM, cp.async double-buffered ----------------
// C = A(MxK,row) * B(NxK,row)^T ; grid=(N/BN, M/BM, splitZ)
template<int BM, int BN, int WM, int WN>
__global__ void __launch_bounds__(256)
gemm_tf32(const float* __restrict__ A, const float* __restrict__ B,
          const float* __restrict__ bias, float* __restrict__ C,
          int M, int N, int K, int kChunk) {
    constexpr int BK = 32;
    constexpr int LD = 36;                 // 32 + 4 pad: conflict-free frag reads
    constexpr int WARPS_N = BN / WN;
    constexpr int MT = WM / 16;
    constexpr int NT = WN / 8;
    constexpr int A_IT = BM / 32;          // float4 chunks per thread per stage
    constexpr int B_IT = BN / 32;

    extern __shared__ float sm[];
    float* Asm = sm;                       // [2][BM][LD]
    float* Bsm = sm + 2 * BM * LD;         // [2][BN][LD]

    const int tid = threadIdx.x;
    const int lane = tid & 31;
    const int warp = tid >> 5;
    const int wr = (warp / WARPS_N) * WM;
    const int wc = (warp % WARPS_N) * WN;
    const int gid = lane >> 2;
    const int tg  = lane & 3;

    const int kBase = blockIdx.z * kChunk;
    const float* Ab = A + (size_t)blockIdx.y * BM * K;
    const float* Bb = B + (size_t)blockIdx.x * BN * K;

    uint32_t aBase = (uint32_t)__cvta_generic_to_shared(Asm);
    uint32_t bBase = (uint32_t)__cvta_generic_to_shared(Bsm);

    auto issue = [&](int it) {
        int s = it & 1;
        int kt = kBase + it * BK;
#pragma unroll
        for (int t = 0; t < A_IT; t++) {
            int lin = tid + t * 256;
            int row = lin >> 3, cv = (lin & 7) << 2;
            const float* src = Ab + (size_t)row * K + kt + cv;
            uint32_t dst = aBase + (uint32_t)(((s * BM + row) * LD + cv) * 4);
            asm volatile("cp.async.cg.shared.global [%0], [%1], 16;\n" :: "r"(dst), "l"(src));
        }
#pragma unroll
        for (int t = 0; t < B_IT; t++) {
            int lin = tid + t * 256;
            int row = lin >> 3, cv = (lin & 7) << 2;
            const float* src = Bb + (size_t)row * K + kt + cv;
            uint32_t dst = bBase + (uint32_t)(((s * BN + row) * LD + cv) * 4);
            asm volatile("cp.async.cg.shared.global [%0], [%1], 16;\n" :: "r"(dst), "l"(src));
        }
        asm volatile("cp.async.commit_group;\n" ::: "memory");
    };

    float c[MT][NT][4];
#pragma unroll
    for (int i = 0; i < MT; i++)
#pragma unroll
        for (int j = 0; j < NT; j++)
#pragma unroll
            for (int r = 0; r < 4; r++) c[i][j][r] = 0.f;

    const int nIt = kChunk / BK;
    issue(0);

    for (int it = 0; it < nIt; it++) {
        asm volatile("cp.async.wait_group 0;\n" ::: "memory");
        __syncthreads();
        if (it + 1 < nIt) issue(it + 1);

        const int s = it & 1;
        const float* As_ = Asm + s * BM * LD;
        const float* Bs_ = Bsm + s * BN * LD;

#pragma unroll
        for (int kk = 0; kk < 4; kk++) {
            uint32_t af[MT][4];
            uint32_t bf[NT][2];
#pragma unroll
            for (int mt = 0; mt < MT; mt++) {
                int row = wr + mt * 16 + gid;
                af[mt][0] = f2tf32(As_[row * LD + kk * 8 + tg]);
                af[mt][1] = f2tf32(As_[(row + 8) * LD + kk * 8 + tg]);
                af[mt][2] = f2tf32(As_[row * LD + kk * 8 + tg + 4]);
                af[mt][3] = f2tf32(As_[(row + 8) * LD + kk * 8 + tg + 4]);
            }
#pragma unroll
            for (int nt = 0; nt < NT; nt++) {
                int col = wc + nt * 8 + gid;
                bf[nt][0] = f2tf32(Bs_[col * LD + kk * 8 + tg]);
                bf[nt][1] = f2tf32(Bs_[col * LD + kk * 8 + tg + 4]);
            }
#pragma unroll
            for (int mt = 0; mt < MT; mt++)
#pragma unroll
                for (int nt = 0; nt < NT; nt++) {
                    asm volatile(
                        "mma.sync.aligned.m16n8k8.row.col.f32.tf32.tf32.f32 "
                        "{%0,%1,%2,%3}, {%4,%5,%6,%7}, {%8,%9}, {%0,%1,%2,%3};\n"
                        : "+f"(c[mt][nt][0]), "+f"(c[mt][nt][1]),
                          "+f"(c[mt][nt][2]), "+f"(c[mt][nt][3])
                        : "r"(af[mt][0]), "r"(af[mt][1]), "r"(af[mt][2]), "r"(af[mt][3]),
                          "r"(bf[nt][0]), "r"(bf[nt][1]));
                }
        }
        __syncthreads();
    }

    const bool addb = (bias != nullptr) && (blockIdx.z == 0);
    float* Cz = C + (size_t)blockIdx.z * M * N;
#pragma unroll
    for (int mt = 0; mt < MT; mt++) {
        int row0 = blockIdx.y * BM + wr + mt * 16 + gid;
#pragma unroll
        for (int nt = 0; nt < NT; nt++) {
            int col = blockIdx.x * BN + wc + nt * 8 + tg * 2;
            float b0 = addb ? bias[col] : 0.f;
            float b1 = addb ? bias[col + 1] : 0.f;
            Cz[(size_t)row0 * N + col]           = c[mt][nt][0] + b0;
            Cz[(size_t)row0 * N + col + 1]       = c[mt][nt][1] + b1;
            Cz[(size_t)(row0 + 8) * N + col]     = c[mt][nt][2] + b0;
            Cz[(size_t)(row0 + 8) * N + col + 1] = c[mt][nt][3] + b1;
        }
    }
}

// ---------------- fp32 fallback GEMM (t2 only, tiny) ----------------
template<int BM, int BN, int TM, int TN>
__global__ void __launch_bounds__(256)
gemm_nt(const float* __restrict__ A, const float* __restrict__ B,
        const float* __restrict__ bias, float* __restrict__ C,
        int M, int N, int K, int kChunk) {
    constexpr int BK = 8;
    __shared__ float As[BK][BM];
    __shared__ float Bs[BK][BN];
    const int tid = threadIdx.x;
    const int kBase = blockIdx.z * kChunk;
    const float* Ab = A + (size_t)blockIdx.y * BM * K + kBase;
    const float* Bb = B + (size_t)blockIdx.x * BN * K + kBase;
    float acc[TM][TN];
#pragma unroll
    for (int i = 0; i < TM; i++)
#pragma unroll
        for (int j = 0; j < TN; j++) acc[i][j] = 0.f;

    const int tRow = (tid / (BN / TN)) * TM;
    const int tCol = (tid % (BN / TN)) * TN;

    for (int kt = 0; kt < kChunk; kt += BK) {
        for (int i = tid; i < BM * 2; i += 256) {
            int row = i >> 1, c4 = (i & 1) << 2;
            float4 v = *(const float4*)(Ab + (size_t)row * K + kt + c4);
            As[c4 + 0][row] = v.x; As[c4 + 1][row] = v.y;
            As[c4 + 2][row] = v.z; As[c4 + 3][row] = v.w;
        }
        for (int i = tid; i < BN * 2; i += 256) {
            int row = i >> 1, c4 = (i & 1) << 2;
            float4 v = *(const float4*)(Bb + (size_t)row * K + kt + c4);
            Bs[c4 + 0][row] = v.x; Bs[c4 + 1][row] = v.y;
            Bs[c4 + 2][row] = v.z; Bs[c4 + 3][row] = v.w;
        }
        __syncthreads();
#pragma unroll
        for (int k = 0; k < BK; k++) {
            float ra[TM], rb[TN];
#pragma unroll
            for (int i = 0; i < TM; i += 4)
                *(float4*)&ra[i] = *(const float4*)&As[k][tRow + i];
#pragma unroll
            for (int j = 0; j < TN; j += 4)
                *(float4*)&rb[j] = *(const float4*)&Bs[k][tCol + j];
#pragma unroll
            for (int i = 0; i < TM; i++)
#pragma unroll
                for (int j = 0; j < TN; j++)
                    acc[i][j] += ra[i] * rb[j];
        }
        __syncthreads();
    }

    float* Cb = C + (size_t)blockIdx.z * M * N
                  + (size_t)(blockIdx.y * BM + tRow) * N + blockIdx.x * BN + tCol;
    const bool addb = (bias != nullptr) && (blockIdx.z == 0);
#pragma unroll
    for (int i = 0; i < TM; i++)
#pragma unroll
        for (int j = 0; j < TN; j++) {
            float v = acc[i][j];
            if (addb) v += bias[blockIdx.x * BN + tCol + j];
            Cb[(size_t)i * N + j] = v;
        }
}

// ---------------- bilinear-resized position biases ----------------
// pb[h][a][n] (stage1); ab[h][a][n] (stage2, a-major for coalesced reads)
__global__ void bias_resize_kernel(const float* __restrict__ an, const float* __restrict__ na,
                                   const float* __restrict__ ah, const float* __restrict__ aw,
                                   const float* __restrict__ ha, const float* __restrict__ wa,
                                   float* __restrict__ pb, float* __restrict__ ab) {
    int i = blockIdx.x * 256 + threadIdx.x;
    if (i >= NHD * NAG * NTOK) return;
    int h = i / (NAG * NTOK);
    int rem = i % (NAG * NTOK);
    int a = rem / NTOK;
    int n = rem % NTOK;
    int r = n / 14, c = n % 14;

    auto coord = [](int j, int& i0, int& i1, float& w) {
        float src = (j + 0.5f) * 0.5f - 0.5f;
        src = fmaxf(src, 0.f);
        src = fminf(src, 6.f);
        i0 = (int)floorf(src);
        i1 = min(i0 + 1, 6);
        w = src - (float)i0;
    };
    int r0, r1, c0, c1; float wr, wc;
    coord(r, r0, r1, wr);
    coord(c, c0, c1, wc);

    const float* T1 = an + ((size_t)h * NAG + a) * 49;
    float v1 = (1.f - wr) * ((1.f - wc) * T1[r0 * 7 + c0] + wc * T1[r0 * 7 + c1])
             + wr * ((1.f - wc) * T1[r1 * 7 + c0] + wc * T1[r1 * 7 + c1]);
    pb[((size_t)h * NAG + a) * NTOK + n] =
        v1 + ah[((size_t)h * NAG + a) * 14 + r] + aw[((size_t)h * NAG + a) * 14 + c];

    const float* T2 = na + ((size_t)h * NAG + a) * 49;
    float v2 = (1.f - wr) * ((1.f - wc) * T2[r0 * 7 + c0] + wc * T2[r0 * 7 + c1])
             + wr * ((1.f - wc) * T2[r1 * 7 + c0] + wc * T2[r1 * 7 + c1]);
    ab[((size_t)h * NAG + a) * NTOK + n] =
        v2 + ha[((size_t)h * 14 + r) * NAG + a] + wa[((size_t)h * 14 + c) * NAG + a];
}

// ---------------- fused agent attention + depthwise conv ----------------
#define LDT 200
__global__ void __launch_bounds__(256)
attn_dwc_kernel(const float* __restrict__ qkv, const float* __restrict__ pb,
                const float* __restrict__ ab, const float* __restrict__ dwc_w,
                const float* __restrict__ dwc_b, float* __restrict__ t_out) {
    __shared__ float qt[8][LDT];
    __shared__ float kt[8][LDT];
    __shared__ float vt[8][LDT];
    __shared__ __align__(16) float ag[392];
    __shared__ __align__(16) float av[392];
    __shared__ float wsm[72];
    __shared__ float bsm[8];

    const int b = blockIdx.x >> 3, h = blockIdx.x & 7;
    const int tid = threadIdx.x;
    const float scale = 0.35355339059327373f;
    const float* base = qkv + (size_t)b * NTOK * 192 + h * 8;

    for (int i = tid; i < 392; i += 256) {
        int n = i >> 1, p = (i & 1) << 2;
        float4 q4 = *(const float4*)(base + n * 192 + p);
        float4 k4 = *(const float4*)(base + n * 192 + 64 + p);
        float4 v4 = *(const float4*)(base + n * 192 + 128 + p);
        qt[p + 0][n] = q4.x; qt[p + 1][n] = q4.y; qt[p + 2][n] = q4.z; qt[p + 3][n] = q4.w;
        kt[p + 0][n] = k4.x; kt[p + 1][n] = k4.y; kt[p + 2][n] = k4.z; kt[p + 3][n] = k4.w;
        vt[p + 0][n] = v4.x; vt[p + 1][n] = v4.y; vt[p + 2][n] = v4.z; vt[p + 3][n] = v4.w;
    }
    if (tid < 72) wsm[tid] = dwc_w[h * 72 + tid];
    if (tid >= 72 && tid < 80) bsm[tid - 72] = dwc_b[h * 8 + tid - 72];
    __syncthreads();

    // agent tokens: 2x2 mean pool of q
    for (int i = tid; i < 392; i += 256) {
        int a = i >> 3, d = i & 7;
        int ar = a / 7, ac = a % 7;
        int n0 = ar * 28 + ac * 2;
        ag[a * 8 + d] = 0.25f * (qt[d][n0] + qt[d][n0 + 1] + qt[d][n0 + 14] + qt[d][n0 + 15]);
    }
    __syncthreads();

    // ---- stage 1: 3 agent rows per pass; k/v loaded once per pass ----
    const int warp = tid >> 5, lane = tid & 31;
    const float* pbh = pb + (size_t)h * NAG * NTOK;
    for (int c0 = 0; c0 < 7; c0 += 3) {
        const int a0 = warp + c0 * 8;
        const int a1 = warp + (c0 + 1) * 8;
        const int a2 = warp + (c0 + 2) * 8;
        const bool v0 = a0 < NAG;
        const bool v1 = (c0 + 1 < 7) && a1 < NAG;
        const bool v2 = (c0 + 2 < 7) && a2 < NAG;
        if (!v0) continue;

        float4 g00 = *(const float4*)(ag + a0 * 8);
        float4 g01 = *(const float4*)(ag + a0 * 8 + 4);
        float4 g10 = {0,0,0,0}, g11 = {0,0,0,0}, g20 = {0,0,0,0}, g21 = {0,0,0,0};
        if (v1) { g10 = *(const float4*)(ag + a1 * 8); g11 = *(const float4*)(ag + a1 * 8 + 4); }
        if (v2) { g20 = *(const float4*)(ag + a2 * 8); g21 = *(const float4*)(ag + a2 * 8 + 4); }

        float e0[7], e1[7], e2[7];
        float m0 = -1e30f, m1 = -1e30f, m2 = -1e30f;
#pragma unroll
        for (int i = 0; i < 7; i++) {
            int n = lane + i * 32;
            bool nv = n < NTOK;
            float k8[8];
#pragma unroll
            for (int d = 0; d < 8; d++) k8[d] = nv ? kt[d][n] : 0.f;
            float s0 = -1e30f, s1 = -1e30f, s2 = -1e30f;
            if (nv) {
                s0 = (g00.x*k8[0] + g00.y*k8[1] + g00.z*k8[2] + g00.w*k8[3]
                    + g01.x*k8[4] + g01.y*k8[5] + g01.z*k8[6] + g01.w*k8[7]) * scale
                    + pbh[a0 * NTOK + n];
                if (v1)
                    s1 = (g10.x*k8[0] + g10.y*k8[1] + g10.z*k8[2] + g10.w*k8[3]
                        + g11.x*k8[4] + g11.y*k8[5] + g11.z*k8[6] + g11.w*k8[7]) * scale
                        + pbh[a1 * NTOK + n];
                if (v2)
                    s2 = (g20.x*k8[0] + g20.y*k8[1] + g20.z*k8[2] + g20.w*k8[3]
                        + g21.x*k8[4] + g21.y*k8[5] + g21.z*k8[6] + g21.w*k8[7]) * scale
                        + pbh[a2 * NTOK + n];
            }
            e0[i] = s0; e1[i] = s1; e2[i] = s2;
            m0 = fmaxf(m0, s0); m1 = fmaxf(m1, s1); m2 = fmaxf(m2, s2);
        }
#pragma unroll
        for (int o = 16; o; o >>= 1) {
            m0 = fmaxf(m0, __shfl_xor_sync(0xffffffffu, m0, o));
            m1 = fmaxf(m1, __shfl_xor_sync(0xffffffffu, m1, o));
            m2 = fmaxf(m2, __shfl_xor_sync(0xffffffffu, m2, o));
        }
        float sum0 = 0.f, sum1 = 0.f, sum2 = 0.f;
        float A0[8], A1[8], A2[8];
#pragma unroll
        for (int d = 0; d < 8; d++) { A0[d] = 0.f; A1[d] = 0.f; A2[d] = 0.f; }
#pragma unroll
        for (int i = 0; i < 7; i++) {
            int n = lane + i * 32;
            bool nv = n < NTOK;
            float v8[8];
#pragma unroll
            for (int d = 0; d < 8; d++) v8[d] = nv ? vt[d][n] : 0.f;
            float p0 = __expf(e0[i] - m0);          // e=-1e30 with finite m -> 0
            sum0 += p0;
#pragma unroll
            for (int d = 0; d < 8; d++) A0[d] += p0 * v8[d];
            if (v1) {
                float p1 = __expf(e1[i] - m1);
                sum1 += p1;
#pragma unroll
                for (int d = 0; d < 8; d++) A1[d] += p1 * v8[d];
            }
            if (v2) {
                float p2 = __expf(e2[i] - m2);
                sum2 += p2;
#pragma unroll
                for (int d = 0; d < 8; d++) A2[d] += p2 * v8[d];
            }
        }
#pragma unroll
        for (int o = 16; o; o >>= 1) {
            sum0 += __shfl_xor_sync(0xffffffffu, sum0, o);
#pragma unroll
            for (int d = 0; d < 8; d++) A0[d] += __shfl_xor_sync(0xffffffffu, A0[d], o);
            if (v1) {
                sum1 += __shfl_xor_sync(0xffffffffu, sum1, o);
#pragma unroll
                for (int d = 0; d < 8; d++) A1[d] += __shfl_xor_sync(0xffffffffu, A1[d], o);
            }
            if (v2) {
                sum2 += __shfl_xor_sync(0xffffffffu, sum2, o);
#pragma unroll
                for (int d = 0; d < 8; d++) A2[d] += __shfl_xor_sync(0xffffffffu, A2[d], o);
            }
        }
        if (lane == 0) {
            float inv0 = 1.f / sum0;
#pragma unroll
            for (int d = 0; d < 8; d++) av[a0 * 8 + d] = A0[d] * inv0;
            if (v1) {
                float inv1 = 1.f / sum1;
#pragma unroll
                for (int d = 0; d < 8; d++) av[a1 * 8 + d] = A1[d] * inv1;
            }
            if (v2) {
                float inv2 = 1.f / sum2;
#pragma unroll
                for (int d = 0; d < 8; d++) av[a2 * 8 + d] = A2[d] * inv2;
            }
        }
    }
    __syncthreads();

    // ---- stage 2 + dwc: thread per token, online softmax, float4 broadcasts ----
    if (tid < NTOK) {
        const int n = tid;
        const float* abh = ab + (size_t)h * NAG * NTOK;   // [a][n] a-major
        float q[8];
#pragma unroll
        for (int d = 0; d < 8; d++) q[d] = qt[d][n] * scale;
        float m = -1e30f, sum = 0.f;
        float o[8];
#pragma unroll
        for (int d = 0; d < 8; d++) o[d] = 0.f;
#pragma unroll 7
        for (int a = 0; a < NAG; a++) {
            float4 ga0 = *(const float4*)(ag + a * 8);
            float4 ga1 = *(const float4*)(ag + a * 8 + 4);
            float s = q[0]*ga0.x + q[1]*ga0.y + q[2]*ga0.z + q[3]*ga0.w
                    + q[4]*ga1.x + q[5]*ga1.y + q[6]*ga1.z + q[7]*ga1.w
                    + abh[a * NTOK + n];
            float mN = fmaxf(m, s);
            float cr = __expf(m - mN);
            float p  = __expf(s - mN);
            m = mN;
            sum = sum * cr + p;
            float4 w0 = *(const float4*)(av + a * 8);
            float4 w1 = *(const float4*)(av + a * 8 + 4);
            o[0] = o[0]*cr + p*w0.x; o[1] = o[1]*cr + p*w0.y;
            o[2] = o[2]*cr + p*w0.z; o[3] = o[3]*cr + p*w0.w;
            o[4] = o[4]*cr + p*w1.x; o[5] = o[5]*cr + p*w1.y;
            o[6] = o[6]*cr + p*w1.z; o[7] = o[7]*cr + p*w1.w;
        }
        float inv = 1.f / sum;

        // depthwise 3x3 conv on v (channel c = h*8+d) + residual
        const int r = n / 14, col = n % 14;
        float res[8];
#pragma unroll
        for (int d = 0; d < 8; d++) res[d] = o[d] * inv + bsm[d];
#pragma unroll
        for (int dr = -1; dr <= 1; dr++) {
            int rr = r + dr;
            if (rr < 0 || rr > 13) continue;
#pragma unroll
            for (int dc = -1; dc <= 1; dc++) {
                int cc = col + dc;
                if (cc < 0 || cc > 13) continue;
                int nn = rr * 14 + cc;
                int kk = (dr + 1) * 3 + (dc + 1);
#pragma unroll
                for (int d = 0; d < 8; d++) res[d] += wsm[d * 9 + kk] * vt[d][nn];
            }
        }
        float* tb = t_out + (size_t)b * 12544 + n * 64 + h * 8;
        float4 r0 = {res[0], res[1], res[2], res[3]};
        float4 r1 = {res[4], res[5], res[6], res[7]};
        *(float4*)tb = r0;
        *(float4*)(tb + 4) = r1;
    }
}

// ---------------- split-K reduces ----------------
__global__ void reduce_adj(const float* __restrict__ part, float* __restrict__ out) {
    int i = blockIdx.x * 256 + threadIdx.x;
    if (i >= 768 * 256) return;
    float s = 0.f;
#pragma unroll
    for (int z = 0; z < 14; z++) s += part[(size_t)z * 768 * 256 + i];
    out[i] = s;
}

__global__ void reduce_tanh(const float* __restrict__ part, float* __restrict__ hbuf) {
    int i = blockIdx.x * 256 + threadIdx.x;
    if (i >= 768 * 256) return;
    float s = 0.f;
#pragma unroll
    for (int z = 0; z < 8; z++) s += part[(size_t)z * 768 * 256 + i];
    hbuf[i] = tanhf(s);
}

__global__ void reduce_t2(const float* __restrict__ part, float* __restrict__ dout) {
    int i = blockIdx.x * 256 + threadIdx.x;
    if (i >= 768 * 128) return;
    float s = 0.f;
#pragma unroll
    for (int z = 0; z < 4; z++) s += part[(size_t)z * 768 * 128 + i];
    int r = i >> 7, j = i & 127;
    int b = r / 3, which = r % 3;
    dout[(size_t)which * 32768 + b * 128 + j] = s;
}

// ---------------- launch ----------------
extern "C" void kernel_launch(void* const* d_in, const int* in_sizes, int n_in,
                              void* d_out, int out_size) {
    (void)in_sizes; (void)n_in; (void)out_size;
    const float* X       = (const float*)d_in[0];
    const float* W_embed = (const float*)d_in[1];
    const float* b_embed = (const float*)d_in[2];
    const float* W_qkv   = (const float*)d_in[3];
    const float* W_proj  = (const float*)d_in[4];
    const float* b_proj  = (const float*)d_in[5];
    const float* dwc_w   = (const float*)d_in[6];
    const float* dwc_b   = (const float*)d_in[7];
    const float* an_bias = (const float*)d_in[8];
    const float* na_bias = (const float*)d_in[9];
    const float* ah_bias = (const float*)d_in[10];
    const float* aw_bias = (const float*)d_in[11];
    const float* ha_bias = (const float*)d_in[12];
    const float* wa_bias = (const float*)d_in[13];
    const float* W_adj   = (const float*)d_in[14];
    const float* b_adj   = (const float*)d_in[15];
    const float* W_t1    = (const float*)d_in[16];
    const float* b_t1    = (const float*)d_in[17];
    const float* W_t2    = (const float*)d_in[18];
    const float* b_t2    = (const float*)d_in[19];
    float* out = (float*)d_out;

    float* ws = nullptr;
    cudaGetSymbolAddress((void**)&ws, g_ws);
    float* xt    = ws + OFF_XT;
    float* qkv   = ws + OFF_QKV;
    float* tbuf  = ws + OFF_T;
    float* oproj = ws + OFF_OPROJ;
    float* pb    = ws + OFF_PB;
    float* ab    = ws + OFF_AB;
    float* hbuf  = ws + OFF_H;
    float* scr   = ws + OFF_SCR;

    const int SMEM_128 = 2 * (128 * 36 + 128 * 36) * 4;   // 73728 B
    const int SMEM_64  = 2 * (128 * 36 + 64 * 36) * 4;    // 55296 B
    cudaFuncSetAttribute(gemm_tf32<128, 128, 64, 32>,
                         cudaFuncAttributeMaxDynamicSharedMemorySize, SMEM_128);
    cudaFuncSetAttribute(gemm_tf32<128, 64, 32, 32>,
                         cudaFuncAttributeMaxDynamicSharedMemorySize, SMEM_64);

    bias_resize_kernel<<<(NHD * NAG * NTOK + 255) / 256, 256>>>(
        an_bias, na_bias, ah_bias, aw_bias, ha_bias, wa_bias, pb, ab);

    // embed: (768,1280) x (12544,1280)^T + b -> xt
    gemm_tf32<128, 128, 64, 32><<<dim3(98, 6, 1), 256, SMEM_128>>>(
        X, W_embed, b_embed, xt, 768, 12544, 1280, 1280);

    // qkv: (150528,64) x (192,64)^T -> qkv
    gemm_tf32<128, 64, 32, 32><<<dim3(3, 1176, 1), 256, SMEM_64>>>(
        xt, W_qkv, nullptr, qkv, 150528, 192, 64, 64);

    // fused agent attention + dwc -> tbuf
    attn_dwc_kernel<<<B3 * NHD, 256>>>(qkv, pb, ab, dwc_w, dwc_b, tbuf);

    // proj: (150528,64) x (64,64)^T + b -> oproj
    gemm_tf32<128, 64, 32, 32><<<dim3(1, 1176, 1), 256, SMEM_64>>>(
        tbuf, W_proj, b_proj, oproj, 150528, 64, 64, 64);

    // adj: (768,12544) x (256,12544)^T + b, split 14 -> scr -> X_adj
    gemm_tf32<128, 128, 64, 32><<<dim3(2, 6, 14), 256, SMEM_128>>>(
        oproj, W_adj, b_adj, scr, 768, 256, 12544, 896);
    reduce_adj<<<768, 256>>>(scr, out + 98304);

    // MLP t1: (768,1280) x (256,1280)^T + b, split 8, tanh -> hbuf
    gemm_tf32<128, 128, 64, 32><<<dim3(2, 6, 8), 256, SMEM_128>>>(
        X, W_t1, b_t1, scr, 768, 256, 1280, 160);
    reduce_tanh<<<768, 256>>>(scr, hbuf);

    // MLP t2: (768,256) x (128,256)^T + b, split 4 -> anchor/pos/neg
    gemm_nt<128, 64, 8, 4><<<dim3(2, 6, 4), 256>>>(
        hbuf, W_t2, b_t2, scr, 768, 128, 256, 64);
    reduce_t2<<<(768 * 128 + 255) / 256, 256>>>(scr, out);
}

// round 9
// speedup vs baseline: 2.6404x; 1.0165x over previous
#include <cuda_runtime.h>
#include <stdint.h>
#include <math.h>

// ---------------- sizes ----------------
// B=256, b3=768, D=1280, C=64, WIN=14, N=196, NH=8, HD=8, A=49
#define B3    768
#define NTOK  196
#define NHD   8
#define NAG   49

constexpr size_t SZ_XT    = 768ull * 12544;
constexpr size_t SZ_QKV   = 768ull * 196 * 192;
constexpr size_t SZ_T     = 768ull * 12544;
constexpr size_t SZ_OPROJ = 768ull * 12544;
constexpr size_t SZ_PB    = 8ull * 49 * 196;
constexpr size_t SZ_AB    = 8ull * 49 * 196;
constexpr size_t SZ_H     = 768ull * 256;
constexpr size_t SZ_SCR   = 28ull * 768 * 256;

constexpr size_t OFF_XT    = 0;
constexpr size_t OFF_QKV   = OFF_XT + SZ_XT;
constexpr size_t OFF_T     = OFF_QKV + SZ_QKV;
constexpr size_t OFF_OPROJ = OFF_T + SZ_T;
constexpr size_t OFF_PB    = OFF_OPROJ + SZ_OPROJ;
constexpr size_t OFF_AB    = OFF_PB + SZ_PB;
constexpr size_t OFF_H     = OFF_AB + SZ_AB;
constexpr size_t OFF_SCR   = OFF_H + SZ_H;
constexpr size_t WS_TOTAL  = OFF_SCR + SZ_SCR;

__device__ __align__(256) float g_ws[WS_TOTAL];

__device__ __forceinline__ uint32_t f2tf32(float x) {
    uint32_t u;
    asm("cvt.rna.tf32.f32 %0, %1;" : "=r"(u) : "f"(x));
    return u;
}

// ---------------- tf32 tensor-core NT GEMM, cp.async double-buffered ----------------
// C = A(MxK,row) * B(NxK,row)^T ; grid=(N/BN, M/BM, splitZ)
template<int BM, int BN, int WM, int WN>
__global__ void __launch_bounds__(256)
gemm_tf32(const float* __restrict__ A, const float* __restrict__ B,
          const float* __restrict__ bias, float* __restrict__ C,
          int M, int N, int K, int kChunk) {
    constexpr int BK = 32;
    constexpr int LD = 36;                 // 32 + 4 pad: conflict-free frag reads
    constexpr int WARPS_N = BN / WN;
    constexpr int MT = WM / 16;
    constexpr int NT = WN / 8;
    constexpr int A_IT = BM / 32;          // float4 chunks per thread per stage
    constexpr int B_IT = BN / 32;

    extern __shared__ float sm[];
    float* Asm = sm;                       // [2][BM][LD]
    float* Bsm = sm + 2 * BM * LD;         // [2][BN][LD]

    const int tid = threadIdx.x;
    const int lane = tid & 31;
    const int warp = tid >> 5;
    const int wr = (warp / WARPS_N) * WM;
    const int wc = (warp % WARPS_N) * WN;
    const int gid = lane >> 2;
    const int tg  = lane & 3;

    const int kBase = blockIdx.z * kChunk;
    const float* Ab = A + (size_t)blockIdx.y * BM * K;
    const float* Bb = B + (size_t)blockIdx.x * BN * K;

    uint32_t aBase = (uint32_t)__cvta_generic_to_shared(Asm);
    uint32_t bBase = (uint32_t)__cvta_generic_to_shared(Bsm);

    auto issue = [&](int it) {
        int s = it & 1;
        int kt = kBase + it * BK;
#pragma unroll
        for (int t = 0; t < A_IT; t++) {
            int lin = tid + t * 256;
            int row = lin >> 3, cv = (lin & 7) << 2;
            const float* src = Ab + (size_t)row * K + kt + cv;
            uint32_t dst = aBase + (uint32_t)(((s * BM + row) * LD + cv) * 4);
            asm volatile("cp.async.cg.shared.global [%0], [%1], 16;\n" :: "r"(dst), "l"(src));
        }
#pragma unroll
        for (int t = 0; t < B_IT; t++) {
            int lin = tid + t * 256;
            int row = lin >> 3, cv = (lin & 7) << 2;
            const float* src = Bb + (size_t)row * K + kt + cv;
            uint32_t dst = bBase + (uint32_t)(((s * BN + row) * LD + cv) * 4);
            asm volatile("cp.async.cg.shared.global [%0], [%1], 16;\n" :: "r"(dst), "l"(src));
        }
        asm volatile("cp.async.commit_group;\n" ::: "memory");
    };

    float c[MT][NT][4];
#pragma unroll
    for (int i = 0; i < MT; i++)
#pragma unroll
        for (int j = 0; j < NT; j++)
#pragma unroll
            for (int r = 0; r < 4; r++) c[i][j][r] = 0.f;

    const int nIt = kChunk / BK;
    issue(0);

    for (int it = 0; it < nIt; it++) {
        asm volatile("cp.async.wait_group 0;\n" ::: "memory");
        __syncthreads();
        if (it + 1 < nIt) issue(it + 1);

        const int s = it & 1;
        const float* As_ = Asm + s * BM * LD;
        const float* Bs_ = Bsm + s * BN * LD;

#pragma unroll
        for (int kk = 0; kk < 4; kk++) {
            uint32_t af[MT][4];
            uint32_t bf[NT][2];
#pragma unroll
            for (int mt = 0; mt < MT; mt++) {
                int row = wr + mt * 16 + gid;
                af[mt][0] = f2tf32(As_[row * LD + kk * 8 + tg]);
                af[mt][1] = f2tf32(As_[(row + 8) * LD + kk * 8 + tg]);
                af[mt][2] = f2tf32(As_[row * LD + kk * 8 + tg + 4]);
                af[mt][3] = f2tf32(As_[(row + 8) * LD + kk * 8 + tg + 4]);
            }
#pragma unroll
            for (int nt = 0; nt < NT; nt++) {
                int col = wc + nt * 8 + gid;
                bf[nt][0] = f2tf32(Bs_[col * LD + kk * 8 + tg]);
                bf[nt][1] = f2tf32(Bs_[col * LD + kk * 8 + tg + 4]);
            }
#pragma unroll
            for (int mt = 0; mt < MT; mt++)
#pragma unroll
                for (int nt = 0; nt < NT; nt++) {
                    asm volatile(
                        "mma.sync.aligned.m16n8k8.row.col.f32.tf32.tf32.f32 "
                        "{%0,%1,%2,%3}, {%4,%5,%6,%7}, {%8,%9}, {%0,%1,%2,%3};\n"
                        : "+f"(c[mt][nt][0]), "+f"(c[mt][nt][1]),
                          "+f"(c[mt][nt][2]), "+f"(c[mt][nt][3])
                        : "r"(af[mt][0]), "r"(af[mt][1]), "r"(af[mt][2]), "r"(af[mt][3]),
                          "r"(bf[nt][0]), "r"(bf[nt][1]));
                }
        }
        __syncthreads();
    }

    const bool addb = (bias != nullptr) && (blockIdx.z == 0);
    float* Cz = C + (size_t)blockIdx.z * M * N;
#pragma unroll
    for (int mt = 0; mt < MT; mt++) {
        int row0 = blockIdx.y * BM + wr + mt * 16 + gid;
#pragma unroll
        for (int nt = 0; nt < NT; nt++) {
            int col = blockIdx.x * BN + wc + nt * 8 + tg * 2;
            float b0 = addb ? bias[col] : 0.f;
            float b1 = addb ? bias[col + 1] : 0.f;
            Cz[(size_t)row0 * N + col]           = c[mt][nt][0] + b0;
            Cz[(size_t)row0 * N + col + 1]       = c[mt][nt][1] + b1;
            Cz[(size_t)(row0 + 8) * N + col]     = c[mt][nt][2] + b0;
            Cz[(size_t)(row0 + 8) * N + col + 1] = c[mt][nt][3] + b1;
        }
    }
}

// ---------------- fp32 fallback GEMM (t2 only, tiny) ----------------
template<int BM, int BN, int TM, int TN>
__global__ void __launch_bounds__(256)
gemm_nt(const float* __restrict__ A, const float* __restrict__ B,
        const float* __restrict__ bias, float* __restrict__ C,
        int M, int N, int K, int kChunk) {
    constexpr int BK = 8;
    __shared__ float As[BK][BM];
    __shared__ float Bs[BK][BN];
    const int tid = threadIdx.x;
    const int kBase = blockIdx.z * kChunk;
    const float* Ab = A + (size_t)blockIdx.y * BM * K + kBase;
    const float* Bb = B + (size_t)blockIdx.x * BN * K + kBase;
    float acc[TM][TN];
#pragma unroll
    for (int i = 0; i < TM; i++)
#pragma unroll
        for (int j = 0; j < TN; j++) acc[i][j] = 0.f;

    const int tRow = (tid / (BN / TN)) * TM;
    const int tCol = (tid % (BN / TN)) * TN;

    for (int kt = 0; kt < kChunk; kt += BK) {
        for (int i = tid; i < BM * 2; i += 256) {
            int row = i >> 1, c4 = (i & 1) << 2;
            float4 v = *(const float4*)(Ab + (size_t)row * K + kt + c4);
            As[c4 + 0][row] = v.x; As[c4 + 1][row] = v.y;
            As[c4 + 2][row] = v.z; As[c4 + 3][row] = v.w;
        }
        for (int i = tid; i < BN * 2; i += 256) {
            int row = i >> 1, c4 = (i & 1) << 2;
            float4 v = *(const float4*)(Bb + (size_t)row * K + kt + c4);
            Bs[c4 + 0][row] = v.x; Bs[c4 + 1][row] = v.y;
            Bs[c4 + 2][row] = v.z; Bs[c4 + 3][row] = v.w;
        }
        __syncthreads();
#pragma unroll
        for (int k = 0; k < BK; k++) {
            float ra[TM], rb[TN];
#pragma unroll
            for (int i = 0; i < TM; i += 4)
                *(float4*)&ra[i] = *(const float4*)&As[k][tRow + i];
#pragma unroll
            for (int j = 0; j < TN; j += 4)
                *(float4*)&rb[j] = *(const float4*)&Bs[k][tCol + j];
#pragma unroll
            for (int i = 0; i < TM; i++)
#pragma unroll
                for (int j = 0; j < TN; j++)
                    acc[i][j] += ra[i] * rb[j];
        }
        __syncthreads();
    }

    float* Cb = C + (size_t)blockIdx.z * M * N
                  + (size_t)(blockIdx.y * BM + tRow) * N + blockIdx.x * BN + tCol;
    const bool addb = (bias != nullptr) && (blockIdx.z == 0);
#pragma unroll
    for (int i = 0; i < TM; i++)
#pragma unroll
        for (int j = 0; j < TN; j++) {
            float v = acc[i][j];
            if (addb) v += bias[blockIdx.x * BN + tCol + j];
            Cb[(size_t)i * N + j] = v;
        }
}

// ---------------- bilinear-resized position biases ----------------
// pb[h][a][n] (stage1); ab[h][a][n] (stage2, a-major for coalesced reads)
__global__ void bias_resize_kernel(const float* __restrict__ an, const float* __restrict__ na,
                                   const float* __restrict__ ah, const float* __restrict__ aw,
                                   const float* __restrict__ ha, const float* __restrict__ wa,
                                   float* __restrict__ pb, float* __restrict__ ab) {
    int i = blockIdx.x * 256 + threadIdx.x;
    if (i >= NHD * NAG * NTOK) return;
    int h = i / (NAG * NTOK);
    int rem = i % (NAG * NTOK);
    int a = rem / NTOK;
    int n = rem % NTOK;
    int r = n / 14, c = n % 14;

    auto coord = [](int j, int& i0, int& i1, float& w) {
        float src = (j + 0.5f) * 0.5f - 0.5f;
        src = fmaxf(src, 0.f);
        src = fminf(src, 6.f);
        i0 = (int)floorf(src);
        i1 = min(i0 + 1, 6);
        w = src - (float)i0;
    };
    int r0, r1, c0, c1; float wr, wc;
    coord(r, r0, r1, wr);
    coord(c, c0, c1, wc);

    const float* T1 = an + ((size_t)h * NAG + a) * 49;
    float v1 = (1.f - wr) * ((1.f - wc) * T1[r0 * 7 + c0] + wc * T1[r0 * 7 + c1])
             + wr * ((1.f - wc) * T1[r1 * 7 + c0] + wc * T1[r1 * 7 + c1]);
    pb[((size_t)h * NAG + a) * NTOK + n] =
        v1 + ah[((size_t)h * NAG + a) * 14 + r] + aw[((size_t)h * NAG + a) * 14 + c];

    const float* T2 = na + ((size_t)h * NAG + a) * 49;
    float v2 = (1.f - wr) * ((1.f - wc) * T2[r0 * 7 + c0] + wc * T2[r0 * 7 + c1])
             + wr * ((1.f - wc) * T2[r1 * 7 + c0] + wc * T2[r1 * 7 + c1]);
    ab[((size_t)h * NAG + a) * NTOK + n] =
        v2 + ha[((size_t)h * 14 + r) * NAG + a] + wa[((size_t)h * 14 + c) * NAG + a];
}

// ---------------- fused agent attention + depthwise conv ----------------
#define LDT 200
__global__ void __launch_bounds__(256)
attn_dwc_kernel(const float* __restrict__ qkv, const float* __restrict__ pb,
                const float* __restrict__ ab, const float* __restrict__ dwc_w,
                const float* __restrict__ dwc_b, float* __restrict__ t_out) {
    __shared__ float qt[8][LDT];
    __shared__ float kt[8][LDT];
    __shared__ float vt[8][LDT];
    __shared__ __align__(16) float ag[392];
    __shared__ __align__(16) float av[392];
    __shared__ float wsm[72];
    __shared__ float bsm[8];

    const int b = blockIdx.x >> 3, h = blockIdx.x & 7;
    const int tid = threadIdx.x;
    const float scale = 0.35355339059327373f;
    const float* base = qkv + (size_t)b * NTOK * 192 + h * 8;

    for (int i = tid; i < 392; i += 256) {
        int n = i >> 1, p = (i & 1) << 2;
        float4 q4 = *(const float4*)(base + n * 192 + p);
        float4 k4 = *(const float4*)(base + n * 192 + 64 + p);
        float4 v4 = *(const float4*)(base + n * 192 + 128 + p);
        qt[p + 0][n] = q4.x; qt[p + 1][n] = q4.y; qt[p + 2][n] = q4.z; qt[p + 3][n] = q4.w;
        kt[p + 0][n] = k4.x; kt[p + 1][n] = k4.y; kt[p + 2][n] = k4.z; kt[p + 3][n] = k4.w;
        vt[p + 0][n] = v4.x; vt[p + 1][n] = v4.y; vt[p + 2][n] = v4.z; vt[p + 3][n] = v4.w;
    }
    if (tid < 72) wsm[tid] = dwc_w[h * 72 + tid];
    if (tid >= 72 && tid < 80) bsm[tid - 72] = dwc_b[h * 8 + tid - 72];
    __syncthreads();

    // agent tokens: 2x2 mean pool of q
    for (int i = tid; i < 392; i += 256) {
        int a = i >> 3, d = i & 7;
        int ar = a / 7, ac = a % 7;
        int n0 = ar * 28 + ac * 2;
        ag[a * 8 + d] = 0.25f * (qt[d][n0] + qt[d][n0 + 1] + qt[d][n0 + 14] + qt[d][n0 + 15]);
    }
    __syncthreads();

    // ---- stage 1: 3 agent rows per pass; k/v loaded once per pass ----
    const int warp = tid >> 5, lane = tid & 31;
    const float* pbh = pb + (size_t)h * NAG * NTOK;
    for (int c0 = 0; c0 < 7; c0 += 3) {
        const int a0 = warp + c0 * 8;
        const int a1 = warp + (c0 + 1) * 8;
        const int a2 = warp + (c0 + 2) * 8;
        const bool v0 = a0 < NAG;
        const bool v1 = (c0 + 1 < 7) && a1 < NAG;
        const bool v2 = (c0 + 2 < 7) && a2 < NAG;
        if (!v0) continue;

        float4 g00 = *(const float4*)(ag + a0 * 8);
        float4 g01 = *(const float4*)(ag + a0 * 8 + 4);
        float4 g10 = {0,0,0,0}, g11 = {0,0,0,0}, g20 = {0,0,0,0}, g21 = {0,0,0,0};
        if (v1) { g10 = *(const float4*)(ag + a1 * 8); g11 = *(const float4*)(ag + a1 * 8 + 4); }
        if (v2) { g20 = *(const float4*)(ag + a2 * 8); g21 = *(const float4*)(ag + a2 * 8 + 4); }

        float e0[7], e1[7], e2[7];
        float m0 = -1e30f, m1 = -1e30f, m2 = -1e30f;
#pragma unroll
        for (int i = 0; i < 7; i++) {
            int n = lane + i * 32;
            bool nv = n < NTOK;
            float k8[8];
#pragma unroll
            for (int d = 0; d < 8; d++) k8[d] = nv ? kt[d][n] : 0.f;
            float s0 = -1e30f, s1 = -1e30f, s2 = -1e30f;
            if (nv) {
                s0 = (g00.x*k8[0] + g00.y*k8[1] + g00.z*k8[2] + g00.w*k8[3]
                    + g01.x*k8[4] + g01.y*k8[5] + g01.z*k8[6] + g01.w*k8[7]) * scale
                    + pbh[a0 * NTOK + n];
                if (v1)
                    s1 = (g10.x*k8[0] + g10.y*k8[1] + g10.z*k8[2] + g10.w*k8[3]
                        + g11.x*k8[4] + g11.y*k8[5] + g11.z*k8[6] + g11.w*k8[7]) * scale
                        + pbh[a1 * NTOK + n];
                if (v2)
                    s2 = (g20.x*k8[0] + g20.y*k8[1] + g20.z*k8[2] + g20.w*k8[3]
                        + g21.x*k8[4] + g21.y*k8[5] + g21.z*k8[6] + g21.w*k8[7]) * scale
                        + pbh[a2 * NTOK + n];
            }
            e0[i] = s0; e1[i] = s1; e2[i] = s2;
            m0 = fmaxf(m0, s0); m1 = fmaxf(m1, s1); m2 = fmaxf(m2, s2);
        }
#pragma unroll
        for (int o = 16; o; o >>= 1) {
            m0 = fmaxf(m0, __shfl_xor_sync(0xffffffffu, m0, o));
            m1 = fmaxf(m1, __shfl_xor_sync(0xffffffffu, m1, o));
            m2 = fmaxf(m2, __shfl_xor_sync(0xffffffffu, m2, o));
        }
        float sum0 = 0.f, sum1 = 0.f, sum2 = 0.f;
        float A0[8], A1[8], A2[8];
#pragma unroll
        for (int d = 0; d < 8; d++) { A0[d] = 0.f; A1[d] = 0.f; A2[d] = 0.f; }
#pragma unroll
        for (int i = 0; i < 7; i++) {
            int n = lane + i * 32;
            bool nv = n < NTOK;
            float v8[8];
#pragma unroll
            for (int d = 0; d < 8; d++) v8[d] = nv ? vt[d][n] : 0.f;
            float p0 = __expf(e0[i] - m0);          // e=-1e30 with finite m -> 0
            sum0 += p0;
#pragma unroll
            for (int d = 0; d < 8; d++) A0[d] += p0 * v8[d];
            if (v1) {
                float p1 = __expf(e1[i] - m1);
                sum1 += p1;
#pragma unroll
                for (int d = 0; d < 8; d++) A1[d] += p1 * v8[d];
            }
            if (v2) {
                float p2 = __expf(e2[i] - m2);
                sum2 += p2;
#pragma unroll
                for (int d = 0; d < 8; d++) A2[d] += p2 * v8[d];
            }
        }
#pragma unroll
        for (int o = 16; o; o >>= 1) {
            sum0 += __shfl_xor_sync(0xffffffffu, sum0, o);
#pragma unroll
            for (int d = 0; d < 8; d++) A0[d] += __shfl_xor_sync(0xffffffffu, A0[d], o);
            if (v1) {
                sum1 += __shfl_xor_sync(0xffffffffu, sum1, o);
#pragma unroll
                for (int d = 0; d < 8; d++) A1[d] += __shfl_xor_sync(0xffffffffu, A1[d], o);
            }
            if (v2) {
                sum2 += __shfl_xor_sync(0xffffffffu, sum2, o);
#pragma unroll
                for (int d = 0; d < 8; d++) A2[d] += __shfl_xor_sync(0xffffffffu, A2[d], o);
            }
        }
        if (lane == 0) {
            float inv0 = 1.f / sum0;
#pragma unroll
            for (int d = 0; d < 8; d++) av[a0 * 8 + d] = A0[d] * inv0;
            if (v1) {
                float inv1 = 1.f / sum1;
#pragma unroll
                for (int d = 0; d < 8; d++) av[a1 * 8 + d] = A1[d] * inv1;
            }
            if (v2) {
                float inv2 = 1.f / sum2;
#pragma unroll
                for (int d = 0; d < 8; d++) av[a2 * 8 + d] = A2[d] * inv2;
            }
        }
    }
    __syncthreads();

    // ---- stage 2 + dwc: thread per token, online softmax, float4 broadcasts ----
    if (tid < NTOK) {
        const int n = tid;
        const float* abh = ab + (size_t)h * NAG * NTOK;   // [a][n] a-major
        float q[8];
#pragma unroll
        for (int d = 0; d < 8; d++) q[d] = qt[d][n] * scale;
        float m = -1e30f, sum = 0.f;
        float o[8];
#pragma unroll
        for (int d = 0; d < 8; d++) o[d] = 0.f;
#pragma unroll 7
        for (int a = 0; a < NAG; a++) {
            float4 ga0 = *(const float4*)(ag + a * 8);
            float4 ga1 = *(const float4*)(ag + a * 8 + 4);
            float s = q[0]*ga0.x + q[1]*ga0.y + q[2]*ga0.z + q[3]*ga0.w
                    + q[4]*ga1.x + q[5]*ga1.y + q[6]*ga1.z + q[7]*ga1.w
                    + abh[a * NTOK + n];
            float mN = fmaxf(m, s);
            float cr = __expf(m - mN);
            float p  = __expf(s - mN);
            m = mN;
            sum = sum * cr + p;
            float4 w0 = *(const float4*)(av + a * 8);
            float4 w1 = *(const float4*)(av + a * 8 + 4);
            o[0] = o[0]*cr + p*w0.x; o[1] = o[1]*cr + p*w0.y;
            o[2] = o[2]*cr + p*w0.z; o[3] = o[3]*cr + p*w0.w;
            o[4] = o[4]*cr + p*w1.x; o[5] = o[5]*cr + p*w1.y;
            o[6] = o[6]*cr + p*w1.z; o[7] = o[7]*cr + p*w1.w;
        }
        float inv = 1.f / sum;

        // depthwise 3x3 conv on v (channel c = h*8+d) + residual
        const int r = n / 14, col = n % 14;
        float res[8];
#pragma unroll
        for (int d = 0; d < 8; d++) res[d] = o[d] * inv + bsm[d];
#pragma unroll
        for (int dr = -1; dr <= 1; dr++) {
            int rr = r + dr;
            if (rr < 0 || rr > 13) continue;
#pragma unroll
            for (int dc = -1; dc <= 1; dc++) {
                int cc = col + dc;
                if (cc < 0 || cc > 13) continue;
                int nn = rr * 14 + cc;
                int kk = (dr + 1) * 3 + (dc + 1);
#pragma unroll
                for (int d = 0; d < 8; d++) res[d] += wsm[d * 9 + kk] * vt[d][nn];
            }
        }
        float* tb = t_out + (size_t)b * 12544 + n * 64 + h * 8;
        float4 r0 = {res[0], res[1], res[2], res[3]};
        float4 r1 = {res[4], res[5], res[6], res[7]};
        *(float4*)tb = r0;
        *(float4*)(tb + 4) = r1;
    }
}

// ---------------- split-K reduces ----------------
__global__ void reduce_adj(const float* __restrict__ part, float* __restrict__ out) {
    int i = blockIdx.x * 256 + threadIdx.x;
    if (i >= 768 * 256) return;
    float s = 0.f;
#pragma unroll
    for (int z = 0; z < 28; z++) s += part[(size_t)z * 768 * 256 + i];
    out[i] = s;
}

__global__ void reduce_tanh(const float* __restrict__ part, float* __restrict__ hbuf) {
    int i = blockIdx.x * 256 + threadIdx.x;
    if (i >= 768 * 256) return;
    float s = 0.f;
#pragma unroll
    for (int z = 0; z < 8; z++) s += part[(size_t)z * 768 * 256 + i];
    hbuf[i] = tanhf(s);
}

__global__ void reduce_t2(const float* __restrict__ part, float* __restrict__ dout) {
    int i = blockIdx.x * 256 + threadIdx.x;
    if (i >= 768 * 128) return;
    float s = 0.f;
#pragma unroll
    for (int z = 0; z < 4; z++) s += part[(size_t)z * 768 * 128 + i];
    int r = i >> 7, j = i & 127;
    int b = r / 3, which = r % 3;
    dout[(size_t)which * 32768 + b * 128 + j] = s;
}

// ---------------- launch ----------------
extern "C" void kernel_launch(void* const* d_in, const int* in_sizes, int n_in,
                              void* d_out, int out_size) {
    (void)in_sizes; (void)n_in; (void)out_size;
    const float* X       = (const float*)d_in[0];
    const float* W_embed = (const float*)d_in[1];
    const float* b_embed = (const float*)d_in[2];
    const float* W_qkv   = (const float*)d_in[3];
    const float* W_proj  = (const float*)d_in[4];
    const float* b_proj  = (const float*)d_in[5];
    const float* dwc_w   = (const float*)d_in[6];
    const float* dwc_b   = (const float*)d_in[7];
    const float* an_bias = (const float*)d_in[8];
    const float* na_bias = (const float*)d_in[9];
    const float* ah_bias = (const float*)d_in[10];
    const float* aw_bias = (const float*)d_in[11];
    const float* ha_bias = (const float*)d_in[12];
    const float* wa_bias = (const float*)d_in[13];
    const float* W_adj   = (const float*)d_in[14];
    const float* b_adj   = (const float*)d_in[15];
    const float* W_t1    = (const float*)d_in[16];
    const float* b_t1    = (const float*)d_in[17];
    const float* W_t2    = (const float*)d_in[18];
    const float* b_t2    = (const float*)d_in[19];
    float* out = (float*)d_out;

    float* ws = nullptr;
    cudaGetSymbolAddress((void**)&ws, g_ws);
    float* xt    = ws + OFF_XT;
    float* qkv   = ws + OFF_QKV;
    float* tbuf  = ws + OFF_T;
    float* oproj = ws + OFF_OPROJ;
    float* pb    = ws + OFF_PB;
    float* ab    = ws + OFF_AB;
    float* hbuf  = ws + OFF_H;
    float* scr   = ws + OFF_SCR;

    const int SMEM_W256 = 2 * (128 * 36 + 256 * 36) * 4;  // 110592 B
    const int SMEM_128  = 2 * (128 * 36 + 128 * 36) * 4;  // 73728 B
    const int SMEM_64   = 2 * (128 * 36 + 64 * 36) * 4;   // 55296 B
    cudaFuncSetAttribute(gemm_tf32<128, 256, 64, 64>,
                         cudaFuncAttributeMaxDynamicSharedMemorySize, SMEM_W256);
    cudaFuncSetAttribute(gemm_tf32<128, 128, 64, 32>,
                         cudaFuncAttributeMaxDynamicSharedMemorySize, SMEM_128);
    cudaFuncSetAttribute(gemm_tf32<128, 64, 32, 32>,
                         cudaFuncAttributeMaxDynamicSharedMemorySize, SMEM_64);

    bias_resize_kernel<<<(NHD * NAG * NTOK + 255) / 256, 256>>>(
        an_bias, na_bias, ah_bias, aw_bias, ha_bias, wa_bias, pb, ab);

    // embed: (768,1280) x (12544,1280)^T + b -> xt   [wide warp tiles]
    gemm_tf32<128, 256, 64, 64><<<dim3(49, 6, 1), 256, SMEM_W256>>>(
        X, W_embed, b_embed, xt, 768, 12544, 1280, 1280);

    // qkv: (150528,64) x (192,64)^T -> qkv
    gemm_tf32<128, 64, 32, 32><<<dim3(3, 1176, 1), 256, SMEM_64>>>(
        xt, W_qkv, nullptr, qkv, 150528, 192, 64, 64);

    // fused agent attention + dwc -> tbuf
    attn_dwc_kernel<<<B3 * NHD, 256>>>(qkv, pb, ab, dwc_w, dwc_b, tbuf);

    // proj: (150528,64) x (64,64)^T + b -> oproj
    gemm_tf32<128, 64, 32, 32><<<dim3(1, 1176, 1), 256, SMEM_64>>>(
        tbuf, W_proj, b_proj, oproj, 150528, 64, 64, 64);

    // adj: (768,12544) x (256,12544)^T + b, BN=256 (W_adj read once), split 28
    gemm_tf32<128, 256, 64, 64><<<dim3(1, 6, 28), 256, SMEM_W256>>>(
        oproj, W_adj, b_adj, scr, 768, 256, 12544, 448);
    reduce_adj<<<768, 256>>>(scr, out + 98304);

    // MLP t1: (768,1280) x (256,1280)^T + b, split 8, tanh -> hbuf
    gemm_tf32<128, 128, 64, 32><<<dim3(2, 6, 8), 256, SMEM_128>>>(
        X, W_t1, b_t1, scr, 768, 256, 1280, 160);
    reduce_tanh<<<768, 256>>>(scr, hbuf);

    // MLP t2: (768,256) x (128,256)^T + b, split 4 -> anchor/pos/neg
    gemm_nt<128, 64, 8, 4><<<dim3(2, 6, 4), 256>>>(
        hbuf, W_t2, b_t2, scr, 768, 128, 256, 64);
    reduce_t2<<<(768 * 128 + 255) / 256, 256>>>(scr, out);
}

// round 12
// speedup vs baseline: 2.7028x; 1.0236x over previous
#include <cuda_runtime.h>
#include <stdint.h>
#include <math.h>

// ---------------- sizes ----------------
// B=256, b3=768, D=1280, C=64, WIN=14, N=196, NH=8, HD=8, A=49
#define B3    768
#define NTOK  196
#define NHD   8
#define NAG   49

constexpr size_t SZ_XT    = 768ull * 12544;
constexpr size_t SZ_QKV   = 768ull * 196 * 192;
constexpr size_t SZ_T     = 768ull * 12544;
constexpr size_t SZ_OPROJ = 768ull * 12544;
constexpr size_t SZ_PB    = 8ull * 49 * 196;
constexpr size_t SZ_AB    = 8ull * 49 * 196;
constexpr size_t SZ_H     = 768ull * 256;
constexpr size_t SZ_SCR   = 28ull * 768 * 256;

constexpr size_t OFF_XT    = 0;
constexpr size_t OFF_QKV   = OFF_XT + SZ_XT;
constexpr size_t OFF_T     = OFF_QKV + SZ_QKV;
constexpr size_t OFF_OPROJ = OFF_T + SZ_T;
constexpr size_t OFF_PB    = OFF_OPROJ + SZ_OPROJ;
constexpr size_t OFF_AB    = OFF_PB + SZ_PB;
constexpr size_t OFF_H     = OFF_AB + SZ_AB;
constexpr size_t OFF_SCR   = OFF_H + SZ_H;
constexpr size_t WS_TOTAL  = OFF_SCR + SZ_SCR;

__device__ __align__(256) float g_ws[WS_TOTAL];

__device__ __forceinline__ uint32_t f2tf32(float x) {
    uint32_t u;
    asm("cvt.rna.tf32.f32 %0, %1;" : "=r"(u) : "f"(x));
    return u;
}

// ---------------- packed f32x2 helpers (sm_103a FFMA2) ----------------
typedef unsigned long long u64;
__device__ __forceinline__ u64 pk2(float lo, float hi) {
    u64 r; asm("mov.b64 %0, {%1,%2};" : "=l"(r) : "f"(lo), "f"(hi)); return r;
}
__device__ __forceinline__ void upk2(u64 v, float& lo, float& hi) {
    asm("mov.b64 {%0,%1}, %2;" : "=f"(lo), "=f"(hi) : "l"(v));
}
__device__ __forceinline__ u64 fma2(u64 a, u64 b, u64 c) {
    u64 d; asm("fma.rn.f32x2 %0, %1, %2, %3;" : "=l"(d) : "l"(a), "l"(b), "l"(c)); return d;
}
__device__ __forceinline__ u64 mul2(u64 a, u64 b) {
    u64 d; asm("mul.rn.f32x2 %0, %1, %2;" : "=l"(d) : "l"(a), "l"(b)); return d;
}
__device__ __forceinline__ u64 add2(u64 a, u64 b) {
    u64 d; asm("add.rn.f32x2 %0, %1, %2;" : "=l"(d) : "l"(a), "l"(b)); return d;
}

// ---------------- tf32 tensor-core NT GEMM, cp.async double-buffered ----------------
template<int BM, int BN, int WM, int WN>
__global__ void __launch_bounds__(256)
gemm_tf32(const float* __restrict__ A, const float* __restrict__ B,
          const float* __restrict__ bias, float* __restrict__ C,
          int M, int N, int K, int kChunk) {
    constexpr int BK = 32;
    constexpr int LD = 36;
    constexpr int WARPS_N = BN / WN;
    constexpr int MT = WM / 16;
    constexpr int NT = WN / 8;
    constexpr int A_IT = BM / 32;
    constexpr int B_IT = BN / 32;

    extern __shared__ float sm[];
    float* Asm = sm;
    float* Bsm = sm + 2 * BM * LD;

    const int tid = threadIdx.x;
    const int lane = tid & 31;
    const int warp = tid >> 5;
    const int wr = (warp / WARPS_N) * WM;
    const int wc = (warp % WARPS_N) * WN;
    const int gid = lane >> 2;
    const int tg  = lane & 3;

    const int kBase = blockIdx.z * kChunk;
    const float* Ab = A + (size_t)blockIdx.y * BM * K;
    const float* Bb = B + (size_t)blockIdx.x * BN * K;

    uint32_t aBase = (uint32_t)__cvta_generic_to_shared(Asm);
    uint32_t bBase = (uint32_t)__cvta_generic_to_shared(Bsm);

    auto issue = [&](int it) {
        int s = it & 1;
        int kt = kBase + it * BK;
#pragma unroll
        for (int t = 0; t < A_IT; t++) {
            int lin = tid + t * 256;
            int row = lin >> 3, cv = (lin & 7) << 2;
            const float* src = Ab + (size_t)row * K + kt + cv;
            uint32_t dst = aBase + (uint32_t)(((s * BM + row) * LD + cv) * 4);
            asm volatile("cp.async.cg.shared.global [%0], [%1], 16;\n" :: "r"(dst), "l"(src));
        }
#pragma unroll
        for (int t = 0; t < B_IT; t++) {
            int lin = tid + t * 256;
            int row = lin >> 3, cv = (lin & 7) << 2;
            const float* src = Bb + (size_t)row * K + kt + cv;
            uint32_t dst = bBase + (uint32_t)(((s * BN + row) * LD + cv) * 4);
            asm volatile("cp.async.cg.shared.global [%0], [%1], 16;\n" :: "r"(dst), "l"(src));
        }
        asm volatile("cp.async.commit_group;\n" ::: "memory");
    };

    float c[MT][NT][4];
#pragma unroll
    for (int i = 0; i < MT; i++)
#pragma unroll
        for (int j = 0; j < NT; j++)
#pragma unroll
            for (int r = 0; r < 4; r++) c[i][j][r] = 0.f;

    const int nIt = kChunk / BK;
    issue(0);

    for (int it = 0; it < nIt; it++) {
        asm volatile("cp.async.wait_group 0;\n" ::: "memory");
        __syncthreads();
        if (it + 1 < nIt) issue(it + 1);

        const int s = it & 1;
        const float* As_ = Asm + s * BM * LD;
        const float* Bs_ = Bsm + s * BN * LD;

#pragma unroll
        for (int kk = 0; kk < 4; kk++) {
            uint32_t af[MT][4];
            uint32_t bf[NT][2];
#pragma unroll
            for (int mt = 0; mt < MT; mt++) {
                int row = wr + mt * 16 + gid;
                af[mt][0] = f2tf32(As_[row * LD + kk * 8 + tg]);
                af[mt][1] = f2tf32(As_[(row + 8) * LD + kk * 8 + tg]);
                af[mt][2] = f2tf32(As_[row * LD + kk * 8 + tg + 4]);
                af[mt][3] = f2tf32(As_[(row + 8) * LD + kk * 8 + tg + 4]);
            }
#pragma unroll
            for (int nt = 0; nt < NT; nt++) {
                int col = wc + nt * 8 + gid;
                bf[nt][0] = f2tf32(Bs_[col * LD + kk * 8 + tg]);
                bf[nt][1] = f2tf32(Bs_[col * LD + kk * 8 + tg + 4]);
            }
#pragma unroll
            for (int mt = 0; mt < MT; mt++)
#pragma unroll
                for (int nt = 0; nt < NT; nt++) {
                    asm volatile(
                        "mma.sync.aligned.m16n8k8.row.col.f32.tf32.tf32.f32 "
                        "{%0,%1,%2,%3}, {%4,%5,%6,%7}, {%8,%9}, {%0,%1,%2,%3};\n"
                        : "+f"(c[mt][nt][0]), "+f"(c[mt][nt][1]),
                          "+f"(c[mt][nt][2]), "+f"(c[mt][nt][3])
                        : "r"(af[mt][0]), "r"(af[mt][1]), "r"(af[mt][2]), "r"(af[mt][3]),
                          "r"(bf[nt][0]), "r"(bf[nt][1]));
                }
        }
        __syncthreads();
    }

    const bool addb = (bias != nullptr) && (blockIdx.z == 0);
    float* Cz = C + (size_t)blockIdx.z * M * N;
#pragma unroll
    for (int mt = 0; mt < MT; mt++) {
        int row0 = blockIdx.y * BM + wr + mt * 16 + gid;
#pragma unroll
        for (int nt = 0; nt < NT; nt++) {
            int col = blockIdx.x * BN + wc + nt * 8 + tg * 2;
            float b0 = addb ? bias[col] : 0.f;
            float b1 = addb ? bias[col + 1] : 0.f;
            Cz[(size_t)row0 * N + col]           = c[mt][nt][0] + b0;
            Cz[(size_t)row0 * N + col + 1]       = c[mt][nt][1] + b1;
            Cz[(size_t)(row0 + 8) * N + col]     = c[mt][nt][2] + b0;
            Cz[(size_t)(row0 + 8) * N + col + 1] = c[mt][nt][3] + b1;
        }
    }
}

// ---------------- fp32 fallback GEMM (t2 only, tiny) ----------------
template<int BM, int BN, int TM, int TN>
__global__ void __launch_bounds__(256)
gemm_nt(const float* __restrict__ A, const float* __restrict__ B,
        const float* __restrict__ bias, float* __restrict__ C,
        int M, int N, int K, int kChunk) {
    constexpr int BK = 8;
    __shared__ float As[BK][BM];
    __shared__ float Bs[BK][BN];
    const int tid = threadIdx.x;
    const int kBase = blockIdx.z * kChunk;
    const float* Ab = A + (size_t)blockIdx.y * BM * K + kBase;
    const float* Bb = B + (size_t)blockIdx.x * BN * K + kBase;
    float acc[TM][TN];
#pragma unroll
    for (int i = 0; i < TM; i++)
#pragma unroll
        for (int j = 0; j < TN; j++) acc[i][j] = 0.f;

    const int tRow = (tid / (BN / TN)) * TM;
    const int tCol = (tid % (BN / TN)) * TN;

    for (int kt = 0; kt < kChunk; kt += BK) {
        for (int i = tid; i < BM * 2; i += 256) {
            int row = i >> 1, c4 = (i & 1) << 2;
            float4 v = *(const float4*)(Ab + (size_t)row * K + kt + c4);
            As[c4 + 0][row] = v.x; As[c4 + 1][row] = v.y;
            As[c4 + 2][row] = v.z; As[c4 + 3][row] = v.w;
        }
        for (int i = tid; i < BN * 2; i += 256) {
            int row = i >> 1, c4 = (i & 1) << 2;
            float4 v = *(const float4*)(Bb + (size_t)row * K + kt + c4);
            Bs[c4 + 0][row] = v.x; Bs[c4 + 1][row] = v.y;
            Bs[c4 + 2][row] = v.z; Bs[c4 + 3][row] = v.w;
        }
        __syncthreads();
#pragma unroll
        for (int k = 0; k < BK; k++) {
            float ra[TM], rb[TN];
#pragma unroll
            for (int i = 0; i < TM; i += 4)
                *(float4*)&ra[i] = *(const float4*)&As[k][tRow + i];
#pragma unroll
            for (int j = 0; j < TN; j += 4)
                *(float4*)&rb[j] = *(const float4*)&Bs[k][tCol + j];
#pragma unroll
            for (int i = 0; i < TM; i++)
#pragma unroll
                for (int j = 0; j < TN; j++)
                    acc[i][j] += ra[i] * rb[j];
        }
        __syncthreads();
    }

    float* Cb = C + (size_t)blockIdx.z * M * N
                  + (size_t)(blockIdx.y * BM + tRow) * N + blockIdx.x * BN + tCol;
    const bool addb = (bias != nullptr) && (blockIdx.z == 0);
#pragma unroll
    for (int i = 0; i < TM; i++)
#pragma unroll
        for (int j = 0; j < TN; j++) {
            float v = acc[i][j];
            if (addb) v += bias[blockIdx.x * BN + tCol + j];
            Cb[(size_t)i * N + j] = v;
        }
}

// ---------------- bilinear-resized position biases ----------------
// pb[h][a][n] (stage1); ab[h][a][n] (stage2, a-major for coalesced reads)
__global__ void bias_resize_kernel(const float* __restrict__ an, const float* __restrict__ na,
                                   const float* __restrict__ ah, const float* __restrict__ aw,
                                   const float* __restrict__ ha, const float* __restrict__ wa,
                                   float* __restrict__ pb, float* __restrict__ ab) {
    int i = blockIdx.x * 256 + threadIdx.x;
    if (i >= NHD * NAG * NTOK) return;
    int h = i / (NAG * NTOK);
    int rem = i % (NAG * NTOK);
    int a = rem / NTOK;
    int n = rem % NTOK;
    int r = n / 14, c = n % 14;

    auto coord = [](int j, int& i0, int& i1, float& w) {
        float src = (j + 0.5f) * 0.5f - 0.5f;
        src = fmaxf(src, 0.f);
        src = fminf(src, 6.f);
        i0 = (int)floorf(src);
        i1 = min(i0 + 1, 6);
        w = src - (float)i0;
    };
    int r0, r1, c0, c1; float wr, wc;
    coord(r, r0, r1, wr);
    coord(c, c0, c1, wc);

    const float* T1 = an + ((size_t)h * NAG + a) * 49;
    float v1 = (1.f - wr) * ((1.f - wc) * T1[r0 * 7 + c0] + wc * T1[r0 * 7 + c1])
             + wr * ((1.f - wc) * T1[r1 * 7 + c0] + wc * T1[r1 * 7 + c1]);
    pb[((size_t)h * NAG + a) * NTOK + n] =
        v1 + ah[((size_t)h * NAG + a) * 14 + r] + aw[((size_t)h * NAG + a) * 14 + c];

    const float* T2 = na + ((size_t)h * NAG + a) * 49;
    float v2 = (1.f - wr) * ((1.f - wc) * T2[r0 * 7 + c0] + wc * T2[r0 * 7 + c1])
             + wr * ((1.f - wc) * T2[r1 * 7 + c0] + wc * T2[r1 * 7 + c1]);
    ab[((size_t)h * NAG + a) * NTOK + n] =
        v2 + ha[((size_t)h * 14 + r) * NAG + a] + wa[((size_t)h * 14 + c) * NAG + a];
}

// ---------------- fused agent attention + depthwise conv (packed f32x2) ----------------
#define LDT 200
__global__ void __launch_bounds__(256)
attn_dwc_kernel(const float* __restrict__ qkv, const float* __restrict__ pb,
                const float* __restrict__ ab, const float* __restrict__ dwc_w,
                const float* __restrict__ dwc_b, float* __restrict__ t_out) {
    // d-dim packed into 4 float2 carriers
    __shared__ float2 q2[4][LDT];
    __shared__ float2 k2[4][LDT];
    __shared__ float2 v2[4][LDT];
    __shared__ __align__(16) float2 ag2[NAG * 4];
    __shared__ __align__(16) float2 av2[NAG * 4];
    __shared__ float2 wsm2[9][4];
    __shared__ float2 bsm2[4];

    const int b = blockIdx.x >> 3, h = blockIdx.x & 7;
    const int tid = threadIdx.x;
    const float scale = 0.35355339059327373f;
    const float* base = qkv + (size_t)b * NTOK * 192 + h * 8;

    for (int i = tid; i < 392; i += 256) {
        int n = i >> 1, half = i & 1;
        int p = half << 1;                    // carrier pair index 0 or 2
        const float* src = base + n * 192 + (half << 2);
        float4 q4 = *(const float4*)(src);
        float4 k4 = *(const float4*)(src + 64);
        float4 v4 = *(const float4*)(src + 128);
        q2[p + 0][n] = make_float2(q4.x, q4.y);
        q2[p + 1][n] = make_float2(q4.z, q4.w);
        k2[p + 0][n] = make_float2(k4.x, k4.y);
        k2[p + 1][n] = make_float2(k4.z, k4.w);
        v2[p + 0][n] = make_float2(v4.x, v4.y);
        v2[p + 1][n] = make_float2(v4.z, v4.w);
    }
    if (tid < 36) {
        int kk = tid >> 2, p = tid & 3;
        wsm2[kk][p] = make_float2(dwc_w[h * 72 + (2 * p) * 9 + kk],
                                  dwc_w[h * 72 + (2 * p + 1) * 9 + kk]);
    } else if (tid < 40) {
        int p = tid - 36;
        bsm2[p] = make_float2(dwc_b[h * 8 + 2 * p], dwc_b[h * 8 + 2 * p + 1]);
    }
    __syncthreads();

    const u64 QUART = pk2(0.25f, 0.25f);

    // agent tokens: 2x2 mean pool of q (packed)
    for (int i = tid; i < 196; i += 256) {
        int a = i >> 2, c = i & 3;
        int ar = a / 7, ac = a % 7;
        int n0 = ar * 28 + ac * 2;
        u64 s = add2(add2(*(const u64*)&q2[c][n0],     *(const u64*)&q2[c][n0 + 1]),
                     add2(*(const u64*)&q2[c][n0 + 14], *(const u64*)&q2[c][n0 + 15]));
        *(u64*)&ag2[a * 4 + c] = mul2(s, QUART);
    }
    __syncthreads();

    // ---- stage 1: 3 agent rows per pass; packed dots + packed AV ----
    const int warp = tid >> 5, lane = tid & 31;
    const float* pbh = pb + (size_t)h * NAG * NTOK;
    for (int c0 = 0; c0 < 7; c0 += 3) {
        const int a0 = warp + c0 * 8;
        const int a1 = warp + (c0 + 1) * 8;
        const int a2 = warp + (c0 + 2) * 8;
        const bool vv1 = (c0 + 1 < 7) && a1 < NAG;
        const bool vv2 = (c0 + 2 < 7) && a2 < NAG;
        if (a0 >= NAG) continue;

        u64 g0c[4], g1c[4], g2c[4];
#pragma unroll
        for (int c = 0; c < 4; c++) {
            g0c[c] = *(const u64*)&ag2[a0 * 4 + c];
            g1c[c] = vv1 ? *(const u64*)&ag2[a1 * 4 + c] : 0ull;
            g2c[c] = vv2 ? *(const u64*)&ag2[a2 * 4 + c] : 0ull;
        }

        float e0[7], e1[7], e2[7];
        float m0 = -1e30f, m1 = -1e30f, m2 = -1e30f;
#pragma unroll
        for (int i = 0; i < 7; i++) {
            int n = lane + i * 32;
            bool nv = n < NTOK;
            int nn = nv ? n : 0;
            u64 kc[4];
#pragma unroll
            for (int c = 0; c < 4; c++) kc[c] = *(const u64*)&k2[c][nn];
            float s0 = -1e30f, s1 = -1e30f, s2 = -1e30f;
            if (nv) {
                u64 t0 = mul2(g0c[0], kc[0]);
                t0 = fma2(g0c[1], kc[1], t0);
                t0 = fma2(g0c[2], kc[2], t0);
                t0 = fma2(g0c[3], kc[3], t0);
                float lx, ly; upk2(t0, lx, ly);
                s0 = (lx + ly) * scale + pbh[a0 * NTOK + n];
                if (vv1) {
                    u64 t1 = mul2(g1c[0], kc[0]);
                    t1 = fma2(g1c[1], kc[1], t1);
                    t1 = fma2(g1c[2], kc[2], t1);
                    t1 = fma2(g1c[3], kc[3], t1);
                    upk2(t1, lx, ly);
                    s1 = (lx + ly) * scale + pbh[a1 * NTOK + n];
                }
                if (vv2) {
                    u64 t2 = mul2(g2c[0], kc[0]);
                    t2 = fma2(g2c[1], kc[1], t2);
                    t2 = fma2(g2c[2], kc[2], t2);
                    t2 = fma2(g2c[3], kc[3], t2);
                    upk2(t2, lx, ly);
                    s2 = (lx + ly) * scale + pbh[a2 * NTOK + n];
                }
            }
            e0[i] = s0; e1[i] = s1; e2[i] = s2;
            m0 = fmaxf(m0, s0); m1 = fmaxf(m1, s1); m2 = fmaxf(m2, s2);
        }
#pragma unroll
        for (int o = 16; o; o >>= 1) {
            m0 = fmaxf(m0, __shfl_xor_sync(0xffffffffu, m0, o));
            m1 = fmaxf(m1, __shfl_xor_sync(0xffffffffu, m1, o));
            m2 = fmaxf(m2, __shfl_xor_sync(0xffffffffu, m2, o));
        }
        float sum0 = 0.f, sum1 = 0.f, sum2 = 0.f;
        u64 A0[4], A1[4], A2[4];
#pragma unroll
        for (int c = 0; c < 4; c++) { A0[c] = 0; A1[c] = 0; A2[c] = 0; }
#pragma unroll
        for (int i = 0; i < 7; i++) {
            int n = lane + i * 32;
            bool nv = n < NTOK;
            int nn = nv ? n : 0;
            u64 vc[4];
#pragma unroll
            for (int c = 0; c < 4; c++) vc[c] = nv ? *(const u64*)&v2[c][nn] : 0ull;
            float p0 = __expf(e0[i] - m0);          // e=-1e30 -> 0
            sum0 += p0;
            u64 p02 = pk2(p0, p0);
#pragma unroll
            for (int c = 0; c < 4; c++) A0[c] = fma2(p02, vc[c], A0[c]);
            if (vv1) {
                float p1 = __expf(e1[i] - m1);
                sum1 += p1;
                u64 p12 = pk2(p1, p1);
#pragma unroll
                for (int c = 0; c < 4; c++) A1[c] = fma2(p12, vc[c], A1[c]);
            }
            if (vv2) {
                float p2 = __expf(e2[i] - m2);
                sum2 += p2;
                u64 p22 = pk2(p2, p2);
#pragma unroll
                for (int c = 0; c < 4; c++) A2[c] = fma2(p22, vc[c], A2[c]);
            }
        }
#pragma unroll
        for (int o = 16; o; o >>= 1) {
            sum0 += __shfl_xor_sync(0xffffffffu, sum0, o);
#pragma unroll
            for (int c = 0; c < 4; c++)
                A0[c] = add2(A0[c], __shfl_xor_sync(0xffffffffu, A0[c], o));
            if (vv1) {
                sum1 += __shfl_xor_sync(0xffffffffu, sum1, o);
#pragma unroll
                for (int c = 0; c < 4; c++)
                    A1[c] = add2(A1[c], __shfl_xor_sync(0xffffffffu, A1[c], o));
            }
            if (vv2) {
                sum2 += __shfl_xor_sync(0xffffffffu, sum2, o);
#pragma unroll
                for (int c = 0; c < 4; c++)
                    A2[c] = add2(A2[c], __shfl_xor_sync(0xffffffffu, A2[c], o));
            }
        }
        if (lane == 0) {
            float inv0 = 1.f / sum0;
#pragma unroll
            for (int c = 0; c < 4; c++) {
                float lx, ly; upk2(A0[c], lx, ly);
                av2[a0 * 4 + c] = make_float2(lx * inv0, ly * inv0);
            }
            if (vv1) {
                float inv1 = 1.f / sum1;
#pragma unroll
                for (int c = 0; c < 4; c++) {
                    float lx, ly; upk2(A1[c], lx, ly);
                    av2[a1 * 4 + c] = make_float2(lx * inv1, ly * inv1);
                }
            }
            if (vv2) {
                float inv2 = 1.f / sum2;
#pragma unroll
                for (int c = 0; c < 4; c++) {
                    float lx, ly; upk2(A2[c], lx, ly);
                    av2[a2 * 4 + c] = make_float2(lx * inv2, ly * inv2);
                }
            }
        }
    }
    __syncthreads();

    // ---- stage 2 + dwc: thread per token, online softmax, packed ----
    if (tid < NTOK) {
        const int n = tid;
        const float* abh = ab + (size_t)h * NAG * NTOK;   // [a][n]
        const u64 scale2 = pk2(scale, scale);
        u64 qc[4];
#pragma unroll
        for (int c = 0; c < 4; c++) qc[c] = mul2(*(const u64*)&q2[c][n], scale2);
        float m = -1e30f, sum = 0.f;
        u64 oc[4] = {0, 0, 0, 0};
#pragma unroll 7
        for (int a = 0; a < NAG; a++) {
            u64 t = mul2(qc[0], *(const u64*)&ag2[a * 4 + 0]);
            t = fma2(qc[1], *(const u64*)&ag2[a * 4 + 1], t);
            t = fma2(qc[2], *(const u64*)&ag2[a * 4 + 2], t);
            t = fma2(qc[3], *(const u64*)&ag2[a * 4 + 3], t);
            float lx, ly; upk2(t, lx, ly);
            float s = lx + ly + abh[a * NTOK + n];
            float mN = fmaxf(m, s);
            float cr = __expf(m - mN);
            float p  = __expf(s - mN);
            m = mN;
            sum = sum * cr + p;
            u64 cr2 = pk2(cr, cr);
            u64 p2p = pk2(p, p);
#pragma unroll
            for (int c = 0; c < 4; c++)
                oc[c] = fma2(oc[c], cr2, mul2(p2p, *(const u64*)&av2[a * 4 + c]));
        }
        float inv = 1.f / sum;
        u64 inv2 = pk2(inv, inv);

        // depthwise 3x3 conv on v + residual (packed)
        const int r = n / 14, col = n % 14;
        u64 resc[4];
#pragma unroll
        for (int c = 0; c < 4; c++)
            resc[c] = fma2(oc[c], inv2, *(const u64*)&bsm2[c]);
#pragma unroll
        for (int dr = -1; dr <= 1; dr++) {
            int rr = r + dr;
            if (rr < 0 || rr > 13) continue;
#pragma unroll
            for (int dc = -1; dc <= 1; dc++) {
                int cc = col + dc;
                if (cc < 0 || cc > 13) continue;
                int nn = rr * 14 + cc;
                int kk = (dr + 1) * 3 + (dc + 1);
#pragma unroll
                for (int c = 0; c < 4; c++)
                    resc[c] = fma2(*(const u64*)&wsm2[kk][c],
                                   *(const u64*)&v2[c][nn], resc[c]);
            }
        }
        float* tb = t_out + (size_t)b * 12544 + n * 64 + h * 8;
        float r0x, r0y, r1x, r1y;
        upk2(resc[0], r0x, r0y); upk2(resc[1], r1x, r1y);
        float4 w0 = {r0x, r0y, r1x, r1y};
        upk2(resc[2], r0x, r0y); upk2(resc[3], r1x, r1y);
        float4 w1 = {r0x, r0y, r1x, r1y};
        *(float4*)tb = w0;
        *(float4*)(tb + 4) = w1;
    }
}

// ---------------- split-K reduces ----------------
__global__ void reduce_adj(const float* __restrict__ part, float* __restrict__ out) {
    int i = blockIdx.x * 256 + threadIdx.x;
    if (i >= 768 * 256) return;
    float s = 0.f;
#pragma unroll
    for (int z = 0; z < 28; z++) s += part[(size_t)z * 768 * 256 + i];
    out[i] = s;
}

__global__ void reduce_tanh(const float* __restrict__ part, float* __restrict__ hbuf) {
    int i = blockIdx.x * 256 + threadIdx.x;
    if (i >= 768 * 256) return;
    float s = 0.f;
#pragma unroll
    for (int z = 0; z < 8; z++) s += part[(size_t)z * 768 * 256 + i];
    hbuf[i] = tanhf(s);
}

__global__ void reduce_t2(const float* __restrict__ part, float* __restrict__ dout) {
    int i = blockIdx.x * 256 + threadIdx.x;
    if (i >= 768 * 128) return;
    float s = 0.f;
#pragma unroll
    for (int z = 0; z < 4; z++) s += part[(size_t)z * 768 * 128 + i];
    int r = i >> 7, j = i & 127;
    int b = r / 3, which = r % 3;
    dout[(size_t)which * 32768 + b * 128 + j] = s;
}

// ---------------- launch ----------------
extern "C" void kernel_launch(void* const* d_in, const int* in_sizes, int n_in,
                              void* d_out, int out_size) {
    (void)in_sizes; (void)n_in; (void)out_size;
    const float* X       = (const float*)d_in[0];
    const float* W_embed = (const float*)d_in[1];
    const float* b_embed = (const float*)d_in[2];
    const float* W_qkv   = (const float*)d_in[3];
    const float* W_proj  = (const float*)d_in[4];
    const float* b_proj  = (const float*)d_in[5];
    const float* dwc_w   = (const float*)d_in[6];
    const float* dwc_b   = (const float*)d_in[7];
    const float* an_bias = (const float*)d_in[8];
    const float* na_bias = (const float*)d_in[9];
    const float* ah_bias = (const float*)d_in[10];
    const float* aw_bias = (const float*)d_in[11];
    const float* ha_bias = (const float*)d_in[12];
    const float* wa_bias = (const float*)d_in[13];
    const float* W_adj   = (const float*)d_in[14];
    const float* b_adj   = (const float*)d_in[15];
    const float* W_t1    = (const float*)d_in[16];
    const float* b_t1    = (const float*)d_in[17];
    const float* W_t2    = (const float*)d_in[18];
    const float* b_t2    = (const float*)d_in[19];
    float* out = (float*)d_out;

    float* ws = nullptr;
    cudaGetSymbolAddress((void**)&ws, g_ws);
    float* xt    = ws + OFF_XT;
    float* qkv   = ws + OFF_QKV;
    float* tbuf  = ws + OFF_T;
    float* oproj = ws + OFF_OPROJ;
    float* pb    = ws + OFF_PB;
    float* ab    = ws + OFF_AB;
    float* hbuf  = ws + OFF_H;
    float* scr   = ws + OFF_SCR;

    const int SMEM_W256 = 2 * (128 * 36 + 256 * 36) * 4;  // 110592 B
    const int SMEM_128  = 2 * (128 * 36 + 128 * 36) * 4;  // 73728 B
    const int SMEM_64   = 2 * (128 * 36 + 64 * 36) * 4;   // 55296 B
    cudaFuncSetAttribute(gemm_tf32<128, 256, 64, 64>,
                         cudaFuncAttributeMaxDynamicSharedMemorySize, SMEM_W256);
    cudaFuncSetAttribute(gemm_tf32<128, 128, 64, 32>,
                         cudaFuncAttributeMaxDynamicSharedMemorySize, SMEM_128);
    cudaFuncSetAttribute(gemm_tf32<128, 64, 32, 32>,
                         cudaFuncAttributeMaxDynamicSharedMemorySize, SMEM_64);

    bias_resize_kernel<<<(NHD * NAG * NTOK + 255) / 256, 256>>>(
        an_bias, na_bias, ah_bias, aw_bias, ha_bias, wa_bias, pb, ab);

    // embed: (768,1280) x (12544,1280)^T + b -> xt
    gemm_tf32<128, 256, 64, 64><<<dim3(49, 6, 1), 256, SMEM_W256>>>(
        X, W_embed, b_embed, xt, 768, 12544, 1280, 1280);

    // qkv: (150528,64) x (192,64)^T -> qkv
    gemm_tf32<128, 64, 32, 32><<<dim3(3, 1176, 1), 256, SMEM_64>>>(
        xt, W_qkv, nullptr, qkv, 150528, 192, 64, 64);

    // fused agent attention + dwc -> tbuf
    attn_dwc_kernel<<<B3 * NHD, 256>>>(qkv, pb, ab, dwc_w, dwc_b, tbuf);

    // proj: (150528,64) x (64,64)^T + b -> oproj
    gemm_tf32<128, 64, 32, 32><<<dim3(1, 1176, 1), 256, SMEM_64>>>(
        tbuf, W_proj, b_proj, oproj, 150528, 64, 64, 64);

    // adj: (768,12544) x (256,12544)^T + b, BN=256, split 28
    gemm_tf32<128, 256, 64, 64><<<dim3(1, 6, 28), 256, SMEM_W256>>>(
        oproj, W_adj, b_adj, scr, 768, 256, 12544, 448);
    reduce_adj<<<768, 256>>>(scr, out + 98304);

    // MLP t1: (768,1280) x (256,1280)^T + b, split 8, tanh -> hbuf
    gemm_tf32<128, 128, 64, 32><<<dim3(2, 6, 8), 256, SMEM_128>>>(
        X, W_t1, b_t1, scr, 768, 256, 1280, 160);
    reduce_tanh<<<768, 256>>>(scr, hbuf);

    // MLP t2: (768,256) x (128,256)^T + b, split 4 -> anchor/pos/neg
    gemm_nt<128, 64, 8, 4><<<dim3(2, 6, 4), 256>>>(
        hbuf, W_t2, b_t2, scr, 768, 128, 256, 64);
    reduce_t2<<<(768 * 128 + 255) / 256, 256>>>(scr, out);
}